// round 14
// baseline (speedup 1.0000x reference)
#include <cuda_runtime.h>
#include <cuda_fp16.h>
#include <cstdint>
#include <math.h>

// Problem constants
#define B_SZ 2
#define L_SEQ 1024
#define D_IN 1024
#define D_MODEL 2048
#define D_STATE 16
#define D_DISCR 128
#define KER 4
#define M_ROWS (B_SZ * L_SEQ)          // 2048
#define N_BCT 256                      // padded: 16 B + 16 C + 128 D1 + 96 zero
#define NCHUNK 16
#define LCHUNK (L_SEQ / NCHUNK)        // 64
#define NCHAN (B_SZ * D_MODEL)         // 4096

// ---------------- scratch (device globals; no allocation) ----------------
__device__ float g_ab[(size_t)M_ROWS * 2 * D_MODEL];      // in_proj out [2048,4096]
__device__ float g_tall[(size_t)M_ROWS * N_BCT];          // [Bm|Cm|t|pad] fp32
__device__ float g_delta[(size_t)M_ROWS * D_MODEL];
__device__ float g_P[(size_t)NCHUNK * NCHAN * D_STATE];
__device__ float g_hend[(size_t)NCHUNK * NCHAN * D_STATE];
__device__ float g_hstart[(size_t)NCHUNK * NCHAN * D_STATE];
// fp16 operands
__device__ __half g_seq_h [(size_t)M_ROWS * D_IN];
__device__ __half g_win_h [(size_t)(2*D_MODEL) * D_IN];
__device__ __half g_a_h   [(size_t)M_ROWS * D_MODEL];
__device__ __half g_wbcd_h[(size_t)N_BCT * D_MODEL];
__device__ __half g_wd2_h [(size_t)D_MODEL * D_DISCR];
__device__ __half g_t_h   [(size_t)M_ROWS * D_DISCR];
__device__ __half g_wout_h[(size_t)D_IN * D_MODEL];
__device__ __half g_y_h   [(size_t)M_ROWS * D_MODEL];

// ================= helpers =================
__device__ __forceinline__ uint32_t smem_u32(const void* p) {
    uint32_t a;
    asm("{ .reg .u64 t; cvta.to.shared.u64 t, %1; cvt.u32.u64 %0, t; }" : "=r"(a) : "l"(p));
    return a;
}
__device__ __forceinline__ void ldm4(uint32_t* r, uint32_t addr) {
    asm volatile("ldmatrix.sync.aligned.m8n8.x4.shared.b16 {%0,%1,%2,%3}, [%4];"
                 : "=r"(r[0]), "=r"(r[1]), "=r"(r[2]), "=r"(r[3]) : "r"(addr));
}
__device__ __forceinline__ void mma16816(float* c, const uint32_t* a, const uint32_t* b) {
    asm volatile("mma.sync.aligned.m16n8k16.row.col.f32.f16.f16.f32 "
                 "{%0,%1,%2,%3}, {%4,%5,%6,%7}, {%8,%9}, {%0,%1,%2,%3};"
                 : "+f"(c[0]), "+f"(c[1]), "+f"(c[2]), "+f"(c[3])
                 : "r"(a[0]), "r"(a[1]), "r"(a[2]), "r"(a[3]), "r"(b[0]), "r"(b[1]));
}
__device__ __forceinline__ void cp16(uint32_t dst, const void* src) {
    asm volatile("cp.async.cg.shared.global [%0], [%1], 16;" :: "r"(dst), "l"(src));
}
__device__ __forceinline__ void cp_commit() {
    asm volatile("cp.async.commit_group;" ::: "memory");
}
template<int N>
__device__ __forceinline__ void cp_wait() {
    asm volatile("cp.async.wait_group %0;" :: "n"(N) : "memory");
}
__device__ __forceinline__ uint32_t swz(int r, int byteCol) {
    uint32_t off = (uint32_t)(r * 128 + byteCol);
    return off ^ (((uint32_t)r & 7u) << 4);
}

// ================= pipelined fp16 HMMA NT GEMM (128x128, BK=64) =============
#define STG 32768
#define NSTG 3
#define GSMEM (NSTG * STG)   // 96 KB

template<int EPI>
__global__ __launch_bounds__(256, 2)
void mma_gemm(int M, int N, int K,
              const __half* __restrict__ A,
              const __half* __restrict__ W,
              float* __restrict__ C,
              const float* __restrict__ bias,
              int kPerSplit)
{
    extern __shared__ char smem[];
    const uint32_t sb = smem_u32(smem);
    const int tid = threadIdx.x;
    const int wid = tid >> 5, lane = tid & 31;
    const int wm = wid & 1, wn = wid >> 1;          // 2 x 4 warp grid
    const int row0 = blockIdx.x * 128;
    const int col0 = blockIdx.y * 128;
    const int k0 = blockIdx.z * kPerSplit;
    const int nCh = kPerSplit / 64;

    const char* Ab = (const char*)A;
    const char* Wb = (const char*)W;

    auto issue = [&](int j) {
        const int st = j % NSTG;
        const uint32_t stA = sb + st * STG;
        const uint32_t stB = stA + 16384;
        const int kt = k0 + j * 64;
#pragma unroll
        for (int i = 0; i < 4; i++) {
            int c = i * 256 + tid;
            int r = c >> 3, g = c & 7;
            cp16(stA + swz(r, g * 16),
                 Ab + ((size_t)(row0 + r) * K + kt) * 2 + g * 16);
        }
#pragma unroll
        for (int i = 0; i < 4; i++) {
            int c = i * 256 + tid;
            int r = c >> 3, g = c & 7;
            cp16(stB + swz(r, g * 16),
                 Wb + ((size_t)(col0 + r) * K + kt) * 2 + g * 16);
        }
        cp_commit();
    };

    float acc[4][4][4];
#pragma unroll
    for (int i = 0; i < 4; i++)
#pragma unroll
        for (int j = 0; j < 4; j++)
#pragma unroll
            for (int q = 0; q < 4; q++) acc[i][j][q] = 0.f;

    const int pre = (nCh < NSTG - 1) ? nCh : (NSTG - 1);
    for (int j = 0; j < pre; j++) issue(j);

    const int ra_l = (lane & 15);
    const int ga_l = (lane >> 4) * 16;
    const int rb_l = ((lane >> 4) & 1) * 8 + (lane & 7);
    const int gb_l = ((lane >> 3) & 1) * 16;

    for (int j = 0; j < nCh; j++) {
        int newer = nCh - 1 - j; if (newer > NSTG - 2) newer = NSTG - 2;
        if (newer >= 1) cp_wait<1>(); else cp_wait<0>();
        __syncthreads();

        if (j + NSTG - 1 < nCh) issue(j + NSTG - 1);

        const int st = j % NSTG;
        const uint32_t sA = sb + st * STG;
        const uint32_t sB = sA + 16384;

#pragma unroll
        for (int s = 0; s < 4; s++) {
            uint32_t ah[4][4], bh[2][4];
#pragma unroll
            for (int mi = 0; mi < 4; mi++) {
                int r = wm * 64 + mi * 16 + ra_l;
                ldm4(ah[mi], sA + swz(r, s * 32 + ga_l));
            }
#pragma unroll
            for (int p = 0; p < 2; p++) {
                int r = wn * 32 + p * 16 + rb_l;
                ldm4(bh[p], sB + swz(r, s * 32 + gb_l));
            }
#pragma unroll
            for (int mi = 0; mi < 4; mi++) {
#pragma unroll
                for (int ni = 0; ni < 4; ni++) {
                    mma16816(acc[mi][ni], ah[mi], &bh[ni >> 1][(ni & 1) * 2]);
                }
            }
        }
    }

    const int er = (lane >> 2);
    const int ec = (lane & 3) * 2;
#pragma unroll
    for (int mi = 0; mi < 4; mi++) {
#pragma unroll
        for (int ni = 0; ni < 4; ni++) {
            int r = row0 + wm * 64 + mi * 16 + er;
            int c = col0 + wn * 32 + ni * 8 + ec;
            float v0 = acc[mi][ni][0], v1 = acc[mi][ni][1];
            float v2 = acc[mi][ni][2], v3 = acc[mi][ni][3];
            if (EPI == 1) {
                float b0 = bias[c], b1 = bias[c + 1];
                float x;
                x = b0 + v0; v0 = (x > 20.f) ? x : log1pf(expf(x));
                x = b1 + v1; v1 = (x > 20.f) ? x : log1pf(expf(x));
                x = b0 + v2; v2 = (x > 20.f) ? x : log1pf(expf(x));
                x = b1 + v3; v3 = (x > 20.f) ? x : log1pf(expf(x));
            }
            if (EPI == 2) {
                atomicAdd(C + (size_t)r * N + c,           v0);
                atomicAdd(C + (size_t)r * N + c + 1,       v1);
                atomicAdd(C + (size_t)(r + 8) * N + c,     v2);
                atomicAdd(C + (size_t)(r + 8) * N + c + 1, v3);
            } else {
                float2 p0 = {v0, v1}, p1 = {v2, v3};
                *(float2*)(C + (size_t)r * N + c)       = p0;
                *(float2*)(C + (size_t)(r + 8) * N + c) = p1;
            }
        }
    }
}

// ============ big-tile GEMM: 256x128, BK=128, 2 stages, optional split-K ====
// Race-free: prologue fills both stages; wait_group<1> retires group j;
// issue(j+2) only after post-compute barrier. EPI: 0 store, 2 atomicAdd.
#define STG_BIG 98304            // 96 KB
#define NSTG_BIG 2
#define GSMEM_BIG (NSTG_BIG * STG_BIG)  // 192 KB

template<int EPI>
__global__ __launch_bounds__(256, 1)
void mma_gemm_big(int M, int N, int K,
                  const __half* __restrict__ A,
                  const __half* __restrict__ W,
                  float* __restrict__ C,
                  int kPerSplit)
{
    extern __shared__ char smem[];
    const uint32_t sb = smem_u32(smem);
    const int tid = threadIdx.x;
    const int wid = tid >> 5, lane = tid & 31;
    const int wm = wid & 3, wn = wid >> 2;          // 4 x 2 warp grid
    const int row0 = blockIdx.x * 256;
    const int col0 = blockIdx.y * 128;
    const int k0 = blockIdx.z * kPerSplit;
    const int nCh = kPerSplit / 128;

    const char* Ab = (const char*)A;
    const char* Wb = (const char*)W;

    auto issue = [&](int j) {
        const int st = j & (NSTG_BIG - 1);
        const uint32_t stA = sb + st * STG_BIG;
        const uint32_t stB = stA + 65536;
        const int kt = k0 + j * 128;
#pragma unroll
        for (int i = 0; i < 16; i++) {
            int c = i * 256 + tid;              // 0..4095
            int r = c >> 4, g = c & 15;
            int half = g >> 3, gg = g & 7;
            cp16(stA + half * 32768 + swz(r, gg * 16),
                 Ab + ((size_t)(row0 + r) * K + kt + g * 8) * 2);
        }
#pragma unroll
        for (int i = 0; i < 8; i++) {
            int c = i * 256 + tid;              // 0..2047
            int r = c >> 4, g = c & 15;
            int half = g >> 3, gg = g & 7;
            cp16(stB + half * 16384 + swz(r, gg * 16),
                 Wb + ((size_t)(col0 + r) * K + kt + g * 8) * 2);
        }
        cp_commit();
    };

    float acc[4][8][4];
#pragma unroll
    for (int i = 0; i < 4; i++)
#pragma unroll
        for (int j = 0; j < 8; j++)
#pragma unroll
            for (int q = 0; q < 4; q++) acc[i][j][q] = 0.f;

    // prologue: fill BOTH stages
    issue(0);
    if (nCh > 1) issue(1);

    const int ra_l = (lane & 15);
    const int ga_l = (lane >> 4) * 16;
    const int rb_l = ((lane >> 4) & 1) * 8 + (lane & 7);
    const int gb_l = ((lane >> 3) & 1) * 16;

    for (int j = 0; j < nCh; j++) {
        if (j + 1 < nCh) cp_wait<1>(); else cp_wait<0>();
        __syncthreads();

        const int st = j & (NSTG_BIG - 1);
        const uint32_t sA = sb + st * STG_BIG;
        const uint32_t sB = sA + 65536;

#pragma unroll
        for (int s = 0; s < 8; s++) {
            const uint32_t hA = sA + (s >> 2) * 32768;
            const uint32_t hB = sB + (s >> 2) * 16384;
            const int so = (s & 3) * 32;
            uint32_t ah[4][4], bh[4][4];
#pragma unroll
            for (int mi = 0; mi < 4; mi++) {
                int r = wm * 64 + mi * 16 + ra_l;
                ldm4(ah[mi], hA + swz(r, so + ga_l));
            }
#pragma unroll
            for (int p = 0; p < 4; p++) {
                int r = wn * 64 + p * 16 + rb_l;
                ldm4(bh[p], hB + swz(r, so + gb_l));
            }
#pragma unroll
            for (int mi = 0; mi < 4; mi++) {
#pragma unroll
                for (int ni = 0; ni < 8; ni++) {
                    mma16816(acc[mi][ni], ah[mi], &bh[ni >> 1][(ni & 1) * 2]);
                }
            }
        }

        if (j + 2 < nCh) {
            __syncthreads();
            issue(j + 2);
        }
    }

    const int er = (lane >> 2);
    const int ec = (lane & 3) * 2;
#pragma unroll
    for (int mi = 0; mi < 4; mi++) {
#pragma unroll
        for (int ni = 0; ni < 8; ni++) {
            int r = row0 + wm * 64 + mi * 16 + er;
            int c = col0 + wn * 64 + ni * 8 + ec;
            float v0 = acc[mi][ni][0], v1 = acc[mi][ni][1];
            float v2 = acc[mi][ni][2], v3 = acc[mi][ni][3];
            if (EPI == 2) {
                atomicAdd(C + (size_t)r * N + c,           v0);
                atomicAdd(C + (size_t)r * N + c + 1,       v1);
                atomicAdd(C + (size_t)(r + 8) * N + c,     v2);
                atomicAdd(C + (size_t)(r + 8) * N + c + 1, v3);
            } else {
                float2 p0 = {v0, v1}, p1 = {v2, v3};
                *(float2*)(C + (size_t)r * N + c)       = p0;
                *(float2*)(C + (size_t)(r + 8) * N + c) = p1;
            }
        }
    }
}

// ================= converts =================
__global__ void convert_fp16_2(const float* __restrict__ X1, __half* __restrict__ Y1, int n1,
                               const float* __restrict__ X2, __half* __restrict__ Y2, int n2)
{
    int idx = blockIdx.x * blockDim.x + threadIdx.x;
    int tot = (n1 + n2) >> 3;
    if (idx >= tot) return;
    const float* X; __half* Y; size_t off;
    if (idx < (n1 >> 3)) { X = X1; Y = Y1; off = (size_t)idx * 8; }
    else { X = X2; Y = Y2; off = (size_t)(idx - (n1 >> 3)) * 8; }
    float4 v0 = *(const float4*)(X + off);
    float4 v1 = *(const float4*)(X + off + 4);
    union { uint4 u; __half h[8]; } o;
    o.h[0] = __float2half_rn(v0.x); o.h[1] = __float2half_rn(v0.y);
    o.h[2] = __float2half_rn(v0.z); o.h[3] = __float2half_rn(v0.w);
    o.h[4] = __float2half_rn(v1.x); o.h[5] = __float2half_rn(v1.y);
    o.h[6] = __float2half_rn(v1.z); o.h[7] = __float2half_rn(v1.w);
    *(uint4*)(Y + off) = o.u;
}

__global__ void build_wbcd(const float* __restrict__ wB, const float* __restrict__ wC,
                           const float* __restrict__ wD1, __half* __restrict__ Y)
{
    int idx = blockIdx.x * blockDim.x + threadIdx.x;
    if (idx >= (N_BCT * D_MODEL) >> 3) return;
    int r = idx / (D_MODEL >> 3);
    int k = (idx % (D_MODEL >> 3)) << 3;
    const float* src = nullptr;
    if (r < 16)       src = wB  + (size_t)r * D_MODEL + k;
    else if (r < 32)  src = wC  + (size_t)(r - 16) * D_MODEL + k;
    else if (r < 160) src = wD1 + (size_t)(r - 32) * D_MODEL + k;
    union { uint4 u; __half h[8]; } o;
    if (src) {
        float4 v0 = *(const float4*)src;
        float4 v1 = *(const float4*)(src + 4);
        o.h[0]=__float2half_rn(v0.x); o.h[1]=__float2half_rn(v0.y);
        o.h[2]=__float2half_rn(v0.z); o.h[3]=__float2half_rn(v0.w);
        o.h[4]=__float2half_rn(v1.x); o.h[5]=__float2half_rn(v1.y);
        o.h[6]=__float2half_rn(v1.z); o.h[7]=__float2half_rn(v1.w);
    } else {
        o.u = make_uint4(0,0,0,0);
    }
    *(uint4*)(Y + (size_t)r * D_MODEL + k) = o.u;
}

__global__ void extract_t(const float* __restrict__ tall, __half* __restrict__ Y)
{
    int idx = blockIdx.x * blockDim.x + threadIdx.x;
    if (idx >= (M_ROWS * D_DISCR) >> 2) return;
    int r = idx / (D_DISCR >> 2);
    int c = (idx % (D_DISCR >> 2)) << 2;
    float4 v = *(const float4*)(tall + (size_t)r * N_BCT + 32 + c);
    union { uint2 u; __half h[4]; } o;
    o.h[0]=__float2half_rn(v.x); o.h[1]=__float2half_rn(v.y);
    o.h[2]=__float2half_rn(v.z); o.h[3]=__float2half_rn(v.w);
    *(uint2*)(Y + (size_t)r * D_DISCR + c) = o.u;
}

// ------ depthwise causal conv (ker=4) + bias + SiLU -> a_h fp16 ------
__global__ void conv_silu_kernel(const float* __restrict__ ab,
                                 const float* __restrict__ cw,
                                 const float* __restrict__ cb,
                                 __half* __restrict__ a_h)
{
    int idx = blockIdx.x * blockDim.x + threadIdx.x;
    if (idx >= B_SZ * L_SEQ * D_MODEL) return;
    int d = idx & (D_MODEL - 1);
    int l = (idx >> 11) & (L_SEQ - 1);
    int b = idx >> 21;

    float w0 = cw[d*4+0], w1 = cw[d*4+1], w2 = cw[d*4+2], w3 = cw[d*4+3];
    const size_t rowBase = ((size_t)b * L_SEQ) * (2*D_MODEL);
    float s = cb[d];
    if (l >= 3) s += w0 * ab[rowBase + (size_t)(l-3)*(2*D_MODEL) + d];
    if (l >= 2) s += w1 * ab[rowBase + (size_t)(l-2)*(2*D_MODEL) + d];
    if (l >= 1) s += w2 * ab[rowBase + (size_t)(l-1)*(2*D_MODEL) + d];
    s += w3 * ab[rowBase + (size_t)l*(2*D_MODEL) + d];
    float v = s / (1.f + expf(-s));
    a_h[idx] = __float2half_rn(v);
}

// ================= chunked scan =================
__global__ __launch_bounds__(128)
void scan_phase1(const float* __restrict__ delta,
                 const __half* __restrict__ a_h,
                 const float* __restrict__ tall,
                 const float* __restrict__ A_param,
                 float* __restrict__ Pb,
                 float* __restrict__ hendb)
{
    int gid = blockIdx.x * blockDim.x + threadIdx.x;
    int ch = gid & (NCHAN - 1);
    int chunk = gid >> 12;
    int b = ch >> 11;
    int d = ch & (D_MODEL - 1);

    float expA[D_STATE];
#pragma unroll
    for (int s = 0; s < D_STATE; s++) expA[s] = expf(-A_param[(size_t)d * D_STATE + s]);

    float h[D_STATE], P[D_STATE];
#pragma unroll
    for (int s = 0; s < D_STATE; s++) { h[s] = 0.f; P[s] = 1.f; }

    const int l0 = chunk * LCHUNK;
    for (int l = l0; l < l0 + LCHUNK; l++) {
        const size_t row = (size_t)b * L_SEQ + l;
        float dlt = delta[row * D_MODEL + d];
        float av  = __half2float(a_h[row * D_MODEL + d]);
        const float4* Bp = (const float4*)(tall + row * N_BCT);
        float4 B0 = Bp[0], B1 = Bp[1], B2 = Bp[2], B3 = Bp[3];
        float Bv[16] = {B0.x,B0.y,B0.z,B0.w, B1.x,B1.y,B1.z,B1.w,
                        B2.x,B2.y,B2.z,B2.w, B3.x,B3.y,B3.z,B3.w};
        float xc = dlt * av;
#pragma unroll
        for (int s = 0; s < D_STATE; s++) {
            float Ab = expA[s] * dlt;
            h[s] = fmaf(Ab, h[s], Bv[s] * xc);
            P[s] *= Ab;
        }
    }
    float4* Pd = (float4*)(Pb    + ((size_t)chunk * NCHAN + ch) * D_STATE);
    float4* Hd = (float4*)(hendb + ((size_t)chunk * NCHAN + ch) * D_STATE);
#pragma unroll
    for (int q = 0; q < 4; q++) {
        Pd[q] = make_float4(P[q*4], P[q*4+1], P[q*4+2], P[q*4+3]);
        Hd[q] = make_float4(h[q*4], h[q*4+1], h[q*4+2], h[q*4+3]);
    }
}

__global__ __launch_bounds__(128)
void scan_phase2(const float* __restrict__ Pb,
                 const float* __restrict__ hendb,
                 float* __restrict__ hstartb)
{
    int ch = blockIdx.x * blockDim.x + threadIdx.x;
    if (ch >= NCHAN) return;
    float hs[D_STATE];
#pragma unroll
    for (int s = 0; s < D_STATE; s++) hs[s] = 0.f;
    for (int c = 0; c < NCHUNK; c++) {
        float4* Hs = (float4*)(hstartb + ((size_t)c * NCHAN + ch) * D_STATE);
#pragma unroll
        for (int q = 0; q < 4; q++)
            Hs[q] = make_float4(hs[q*4], hs[q*4+1], hs[q*4+2], hs[q*4+3]);
        const float4* Pd = (const float4*)(Pb    + ((size_t)c * NCHAN + ch) * D_STATE);
        const float4* He = (const float4*)(hendb + ((size_t)c * NCHAN + ch) * D_STATE);
#pragma unroll
        for (int q = 0; q < 4; q++) {
            float4 p = Pd[q], e = He[q];
            hs[q*4+0] = fmaf(p.x, hs[q*4+0], e.x);
            hs[q*4+1] = fmaf(p.y, hs[q*4+1], e.y);
            hs[q*4+2] = fmaf(p.z, hs[q*4+2], e.z);
            hs[q*4+3] = fmaf(p.w, hs[q*4+3], e.w);
        }
    }
}

__global__ __launch_bounds__(128)
void scan_phase3(const float* __restrict__ delta,
                 const __half* __restrict__ a_h,
                 const float* __restrict__ ab,
                 const float* __restrict__ tall,
                 const float* __restrict__ A_param,
                 const float* __restrict__ D_param,
                 const float* __restrict__ hstartb,
                 __half* __restrict__ y_h)
{
    int gid = blockIdx.x * blockDim.x + threadIdx.x;
    int ch = gid & (NCHAN - 1);
    int chunk = gid >> 12;
    int b = ch >> 11;
    int d = ch & (D_MODEL - 1);

    float expA[D_STATE];
#pragma unroll
    for (int s = 0; s < D_STATE; s++) expA[s] = expf(-A_param[(size_t)d * D_STATE + s]);
    const float Dp = D_param[d];

    float h[D_STATE];
    const float4* Hs = (const float4*)(hstartb + ((size_t)chunk * NCHAN + ch) * D_STATE);
#pragma unroll
    for (int q = 0; q < 4; q++) {
        float4 v = Hs[q];
        h[q*4+0] = v.x; h[q*4+1] = v.y; h[q*4+2] = v.z; h[q*4+3] = v.w;
    }

    const int l0 = chunk * LCHUNK;
    for (int l = l0; l < l0 + LCHUNK; l++) {
        const size_t row = (size_t)b * L_SEQ + l;
        float dlt = delta[row * D_MODEL + d];
        float av  = __half2float(a_h[row * D_MODEL + d]);
        float gt  = ab[row * (2*D_MODEL) + D_MODEL + d];
        const float4* Bp = (const float4*)(tall + row * N_BCT);
        const float4* Cp = (const float4*)(tall + row * N_BCT + 16);
        float4 B0 = Bp[0], B1 = Bp[1], B2 = Bp[2], B3 = Bp[3];
        float4 C0 = Cp[0], C1 = Cp[1], C2 = Cp[2], C3 = Cp[3];
        float Bv[16] = {B0.x,B0.y,B0.z,B0.w, B1.x,B1.y,B1.z,B1.w,
                        B2.x,B2.y,B2.z,B2.w, B3.x,B3.y,B3.z,B3.w};
        float Cv[16] = {C0.x,C0.y,C0.z,C0.w, C1.x,C1.y,C1.z,C1.w,
                        C2.x,C2.y,C2.z,C2.w, C3.x,C3.y,C3.z,C3.w};
        float xc = dlt * av;
        float acc0 = 0.f, acc1 = 0.f;
#pragma unroll
        for (int s = 0; s < D_STATE; s += 2) {
            float Ab0 = expA[s]   * dlt;
            float Ab1 = expA[s+1] * dlt;
            h[s]   = fmaf(Ab0, h[s],   Bv[s]   * xc);
            h[s+1] = fmaf(Ab1, h[s+1], Bv[s+1] * xc);
            acc0   = fmaf(h[s],   Cv[s],   acc0);
            acc1   = fmaf(h[s+1], Cv[s+1], acc1);
        }
        float silu_g = gt / (1.f + expf(-gt));
        float yv = (acc0 + acc1 + Dp * av) * silu_g;
        y_h[row * D_MODEL + d] = __float2half_rn(yv);
    }
}

// ---------------- launch ----------------
extern "C" void kernel_launch(void* const* d_in, const int* in_sizes, int n_in,
                              void* d_out, int out_size)
{
    const float* seq     = (const float*)d_in[0];
    const float* w_in    = (const float*)d_in[1];
    const float* w_out   = (const float*)d_in[2];
    const float* w_B     = (const float*)d_in[3];
    const float* w_C     = (const float*)d_in[4];
    const float* w_D1    = (const float*)d_in[5];
    const float* w_D2    = (const float*)d_in[6];
    const float* conv_w  = (const float*)d_in[7];
    const float* conv_b  = (const float*)d_in[8];
    const float* A_param = (const float*)d_in[9];
    const float* D_param = (const float*)d_in[10];
    float* out = (float*)d_out;

    float *ab_p, *tall_p, *delta_p, *P_p, *hend_p, *hstart_p;
    __half *seq_h, *win_h, *a_h, *wbcd_h, *wd2_h, *t_h, *wout_h, *y_h;
    cudaGetSymbolAddress((void**)&ab_p,    g_ab);
    cudaGetSymbolAddress((void**)&tall_p,  g_tall);
    cudaGetSymbolAddress((void**)&delta_p, g_delta);
    cudaGetSymbolAddress((void**)&P_p,     g_P);
    cudaGetSymbolAddress((void**)&hend_p,  g_hend);
    cudaGetSymbolAddress((void**)&hstart_p,g_hstart);
    cudaGetSymbolAddress((void**)&seq_h,   g_seq_h);
    cudaGetSymbolAddress((void**)&win_h,   g_win_h);
    cudaGetSymbolAddress((void**)&a_h,     g_a_h);
    cudaGetSymbolAddress((void**)&wbcd_h,  g_wbcd_h);
    cudaGetSymbolAddress((void**)&wd2_h,   g_wd2_h);
    cudaGetSymbolAddress((void**)&t_h,     g_t_h);
    cudaGetSymbolAddress((void**)&wout_h,  g_wout_h);
    cudaGetSymbolAddress((void**)&y_h,     g_y_h);

    cudaFuncSetAttribute(mma_gemm<0>, cudaFuncAttributeMaxDynamicSharedMemorySize, GSMEM);
    cudaFuncSetAttribute(mma_gemm<1>, cudaFuncAttributeMaxDynamicSharedMemorySize, GSMEM);
    cudaFuncSetAttribute(mma_gemm<2>, cudaFuncAttributeMaxDynamicSharedMemorySize, GSMEM);
    cudaFuncSetAttribute(mma_gemm_big<0>, cudaFuncAttributeMaxDynamicSharedMemorySize, GSMEM_BIG);
    cudaFuncSetAttribute(mma_gemm_big<2>, cudaFuncAttributeMaxDynamicSharedMemorySize, GSMEM_BIG);

    static cudaStream_t s2 = nullptr;
    static cudaEvent_t evFork = nullptr, evJoin = nullptr;
    if (s2 == nullptr) {
        cudaStreamCreateWithFlags(&s2, cudaStreamNonBlocking);
        cudaEventCreateWithFlags(&evFork, cudaEventDisableTiming);
        cudaEventCreateWithFlags(&evJoin, cudaEventDisableTiming);
    }

    // fork: side stream converts weights not needed until step 3+
    cudaEventRecord(evFork, 0);
    cudaStreamWaitEvent(s2, evFork, 0);
    convert_fp16_2<<<(((D_MODEL*D_DISCR + D_IN*D_MODEL) >> 3) + 255)/256, 256, 0, s2>>>(
        w_D2, wd2_h, D_MODEL * D_DISCR, w_out, wout_h, D_IN * D_MODEL);
    build_wbcd<<<((N_BCT*D_MODEL >> 3) + 255)/256, 256, 0, s2>>>(w_B, w_C, w_D1, wbcd_h);
    cudaEventRecord(evJoin, s2);

    // main stream: converts needed immediately (fused into one launch)
    convert_fp16_2<<<(((M_ROWS*D_IN + 2*D_MODEL*D_IN) >> 3) + 255)/256, 256>>>(
        seq, seq_h, M_ROWS * D_IN, w_in, win_h, 2*D_MODEL * D_IN);

    // 1) in_proj: ab = seq @ w_in^T   (2048 x 4096, K=1024) — big tile
    {
        dim3 grid(M_ROWS/256, (2*D_MODEL)/128, 1);
        mma_gemm_big<0><<<grid, 256, GSMEM_BIG>>>(M_ROWS, 2*D_MODEL, D_IN,
                                                  seq_h, win_h, ab_p, D_IN);
    }
    // 2) depthwise conv + bias + silu -> a_h fp16
    {
        int n = B_SZ * L_SEQ * D_MODEL;
        conv_silu_kernel<<<(n + 255)/256, 256>>>(ab_p, conv_w, conv_b, a_h);
    }
    cudaMemsetAsync(tall_p, 0, (size_t)M_ROWS * N_BCT * sizeof(float));

    cudaStreamWaitEvent(0, evJoin, 0);

    // 3) fused BCt: t_all = a @ [w_B|w_C|w_D1|0]^T  (2048 x 256, K=2048) — big tile, split-K=8
    {
        dim3 grid(M_ROWS/256, N_BCT/128, 8);
        mma_gemm_big<2><<<grid, 256, GSMEM_BIG>>>(M_ROWS, N_BCT, D_MODEL,
                                                  a_h, wbcd_h, tall_p, D_MODEL/8);
    }
    // 4) t -> fp16
    extract_t<<<((M_ROWS*D_DISCR >> 2) + 255)/256, 256>>>(tall_p, t_h);
    // 5) delta = softplus(D_param + t @ w_D2^T)   (2048 x 2048, K=128)
    {
        dim3 grid(M_ROWS/128, D_MODEL/128, 1);
        mma_gemm<1><<<grid, 256, GSMEM>>>(M_ROWS, D_MODEL, D_DISCR,
                                          t_h, wd2_h, delta_p, D_param, D_DISCR);
    }
    // 6) chunked scan
    scan_phase1<<<(NCHAN*NCHUNK)/128, 128>>>(delta_p, a_h, tall_p, A_param, P_p, hend_p);
    scan_phase2<<<NCHAN/128, 128>>>(P_p, hend_p, hstart_p);
    scan_phase3<<<(NCHAN*NCHUNK)/128, 128>>>(delta_p, a_h, ab_p, tall_p,
                                             A_param, D_param, hstart_p, y_h);
    // 7) out = y @ w_out^T  (2048 x 1024, K=2048) — big tile, split-K=2
    cudaMemsetAsync(out, 0, (size_t)M_ROWS * D_IN * sizeof(float));
    {
        dim3 grid(M_ROWS/256, D_IN/128, 2);
        mma_gemm_big<2><<<grid, 256, GSMEM_BIG>>>(M_ROWS, D_IN, D_MODEL,
                                                  y_h, wout_h, out, D_MODEL/2);
    }
}

// round 15
// speedup vs baseline: 1.0177x; 1.0177x over previous
#include <cuda_runtime.h>
#include <cuda_fp16.h>
#include <cstdint>
#include <math.h>

// Problem constants
#define B_SZ 2
#define L_SEQ 1024
#define D_IN 1024
#define D_MODEL 2048
#define D_STATE 16
#define D_DISCR 128
#define KER 4
#define M_ROWS (B_SZ * L_SEQ)          // 2048
#define N_BCT 256                      // padded: 16 B + 16 C + 128 D1 + 96 zero
#define NCHUNK 16
#define LCHUNK (L_SEQ / NCHUNK)        // 64
#define NCHAN (B_SZ * D_MODEL)         // 4096

// ---------------- scratch (device globals; no allocation) ----------------
__device__ float g_ab[(size_t)M_ROWS * 2 * D_MODEL];      // in_proj out [2048,4096]
__device__ float g_tall[(size_t)M_ROWS * N_BCT];          // [Bm|Cm|t|pad] fp32
__device__ float g_delta[(size_t)M_ROWS * D_MODEL];
__device__ float g_P[(size_t)NCHUNK * NCHAN * D_STATE];
__device__ float g_hend[(size_t)NCHUNK * NCHAN * D_STATE];
__device__ float g_hstart[(size_t)NCHUNK * NCHAN * D_STATE];
__device__ float g_outp[(size_t)2 * M_ROWS * D_IN];       // out_proj split-K partials
// fp16 operands
__device__ __half g_seq_h [(size_t)M_ROWS * D_IN];
__device__ __half g_win_h [(size_t)(2*D_MODEL) * D_IN];
__device__ __half g_a_h   [(size_t)M_ROWS * D_MODEL];
__device__ __half g_wbcd_h[(size_t)N_BCT * D_MODEL];
__device__ __half g_wd2_h [(size_t)D_MODEL * D_DISCR];
__device__ __half g_t_h   [(size_t)M_ROWS * D_DISCR];
__device__ __half g_wout_h[(size_t)D_IN * D_MODEL];
__device__ __half g_y_h   [(size_t)M_ROWS * D_MODEL];

// ================= helpers =================
__device__ __forceinline__ uint32_t smem_u32(const void* p) {
    uint32_t a;
    asm("{ .reg .u64 t; cvta.to.shared.u64 t, %1; cvt.u32.u64 %0, t; }" : "=r"(a) : "l"(p));
    return a;
}
__device__ __forceinline__ void ldm4(uint32_t* r, uint32_t addr) {
    asm volatile("ldmatrix.sync.aligned.m8n8.x4.shared.b16 {%0,%1,%2,%3}, [%4];"
                 : "=r"(r[0]), "=r"(r[1]), "=r"(r[2]), "=r"(r[3]) : "r"(addr));
}
__device__ __forceinline__ void mma16816(float* c, const uint32_t* a, const uint32_t* b) {
    asm volatile("mma.sync.aligned.m16n8k16.row.col.f32.f16.f16.f32 "
                 "{%0,%1,%2,%3}, {%4,%5,%6,%7}, {%8,%9}, {%0,%1,%2,%3};"
                 : "+f"(c[0]), "+f"(c[1]), "+f"(c[2]), "+f"(c[3])
                 : "r"(a[0]), "r"(a[1]), "r"(a[2]), "r"(a[3]), "r"(b[0]), "r"(b[1]));
}
__device__ __forceinline__ void cp16(uint32_t dst, const void* src) {
    asm volatile("cp.async.cg.shared.global [%0], [%1], 16;" :: "r"(dst), "l"(src));
}
__device__ __forceinline__ void cp_commit() {
    asm volatile("cp.async.commit_group;" ::: "memory");
}
template<int N>
__device__ __forceinline__ void cp_wait() {
    asm volatile("cp.async.wait_group %0;" :: "n"(N) : "memory");
}
__device__ __forceinline__ uint32_t swz(int r, int byteCol) {
    uint32_t off = (uint32_t)(r * 128 + byteCol);
    return off ^ (((uint32_t)r & 7u) << 4);
}

// ================= pipelined fp16 HMMA NT GEMM (128x128, BK=64) =============
#define STG 32768
#define NSTG 3
#define GSMEM (NSTG * STG)   // 96 KB

template<int EPI>
__global__ __launch_bounds__(256, 2)
void mma_gemm(int M, int N, int K,
              const __half* __restrict__ A,
              const __half* __restrict__ W,
              float* __restrict__ C,
              const float* __restrict__ bias,
              int kPerSplit)
{
    extern __shared__ char smem[];
    const uint32_t sb = smem_u32(smem);
    const int tid = threadIdx.x;
    const int wid = tid >> 5, lane = tid & 31;
    const int wm = wid & 1, wn = wid >> 1;          // 2 x 4 warp grid
    const int row0 = blockIdx.x * 128;
    const int col0 = blockIdx.y * 128;
    const int k0 = blockIdx.z * kPerSplit;
    const int nCh = kPerSplit / 64;

    const char* Ab = (const char*)A;
    const char* Wb = (const char*)W;

    auto issue = [&](int j) {
        const int st = j % NSTG;
        const uint32_t stA = sb + st * STG;
        const uint32_t stB = stA + 16384;
        const int kt = k0 + j * 64;
#pragma unroll
        for (int i = 0; i < 4; i++) {
            int c = i * 256 + tid;
            int r = c >> 3, g = c & 7;
            cp16(stA + swz(r, g * 16),
                 Ab + ((size_t)(row0 + r) * K + kt) * 2 + g * 16);
        }
#pragma unroll
        for (int i = 0; i < 4; i++) {
            int c = i * 256 + tid;
            int r = c >> 3, g = c & 7;
            cp16(stB + swz(r, g * 16),
                 Wb + ((size_t)(col0 + r) * K + kt) * 2 + g * 16);
        }
        cp_commit();
    };

    float acc[4][4][4];
#pragma unroll
    for (int i = 0; i < 4; i++)
#pragma unroll
        for (int j = 0; j < 4; j++)
#pragma unroll
            for (int q = 0; q < 4; q++) acc[i][j][q] = 0.f;

    const int pre = (nCh < NSTG - 1) ? nCh : (NSTG - 1);
    for (int j = 0; j < pre; j++) issue(j);

    const int ra_l = (lane & 15);
    const int ga_l = (lane >> 4) * 16;
    const int rb_l = ((lane >> 4) & 1) * 8 + (lane & 7);
    const int gb_l = ((lane >> 3) & 1) * 16;

    for (int j = 0; j < nCh; j++) {
        int newer = nCh - 1 - j; if (newer > NSTG - 2) newer = NSTG - 2;
        if (newer >= 1) cp_wait<1>(); else cp_wait<0>();
        __syncthreads();

        if (j + NSTG - 1 < nCh) issue(j + NSTG - 1);

        const int st = j % NSTG;
        const uint32_t sA = sb + st * STG;
        const uint32_t sB = sA + 16384;

#pragma unroll
        for (int s = 0; s < 4; s++) {
            uint32_t ah[4][4], bh[2][4];
#pragma unroll
            for (int mi = 0; mi < 4; mi++) {
                int r = wm * 64 + mi * 16 + ra_l;
                ldm4(ah[mi], sA + swz(r, s * 32 + ga_l));
            }
#pragma unroll
            for (int p = 0; p < 2; p++) {
                int r = wn * 32 + p * 16 + rb_l;
                ldm4(bh[p], sB + swz(r, s * 32 + gb_l));
            }
#pragma unroll
            for (int mi = 0; mi < 4; mi++) {
#pragma unroll
                for (int ni = 0; ni < 4; ni++) {
                    mma16816(acc[mi][ni], ah[mi], &bh[ni >> 1][(ni & 1) * 2]);
                }
            }
        }
    }

    const int er = (lane >> 2);
    const int ec = (lane & 3) * 2;
#pragma unroll
    for (int mi = 0; mi < 4; mi++) {
#pragma unroll
        for (int ni = 0; ni < 4; ni++) {
            int r = row0 + wm * 64 + mi * 16 + er;
            int c = col0 + wn * 32 + ni * 8 + ec;
            float v0 = acc[mi][ni][0], v1 = acc[mi][ni][1];
            float v2 = acc[mi][ni][2], v3 = acc[mi][ni][3];
            if (EPI == 1) {
                float b0 = bias[c], b1 = bias[c + 1];
                float x;
                x = b0 + v0; v0 = (x > 20.f) ? x : log1pf(expf(x));
                x = b1 + v1; v1 = (x > 20.f) ? x : log1pf(expf(x));
                x = b0 + v2; v2 = (x > 20.f) ? x : log1pf(expf(x));
                x = b1 + v3; v3 = (x > 20.f) ? x : log1pf(expf(x));
            }
            if (EPI == 2) {
                atomicAdd(C + (size_t)r * N + c,           v0);
                atomicAdd(C + (size_t)r * N + c + 1,       v1);
                atomicAdd(C + (size_t)(r + 8) * N + c,     v2);
                atomicAdd(C + (size_t)(r + 8) * N + c + 1, v3);
            } else {
                float2 p0 = {v0, v1}, p1 = {v2, v3};
                *(float2*)(C + (size_t)r * N + c)       = p0;
                *(float2*)(C + (size_t)(r + 8) * N + c) = p1;
            }
        }
    }
}

// ============ big-tile GEMM: 256x128, BK=128, 2 stages, optional split-K ====
// Race-free: prologue fills both stages; wait_group<1> retires group j;
// issue(j+2) only after post-compute barrier.
// EPI 0: plain store; gridDim.z>1 writes to per-split partial slice of C.
#define STG_BIG 98304            // 96 KB
#define NSTG_BIG 2
#define GSMEM_BIG (NSTG_BIG * STG_BIG)  // 192 KB

__global__ __launch_bounds__(256, 1)
void mma_gemm_big(int M, int N, int K,
                  const __half* __restrict__ A,
                  const __half* __restrict__ W,
                  float* __restrict__ C,
                  int kPerSplit)
{
    extern __shared__ char smem[];
    const uint32_t sb = smem_u32(smem);
    const int tid = threadIdx.x;
    const int wid = tid >> 5, lane = tid & 31;
    const int wm = wid & 3, wn = wid >> 2;          // 4 x 2 warp grid
    const int row0 = blockIdx.x * 256;
    const int col0 = blockIdx.y * 128;
    const int k0 = blockIdx.z * kPerSplit;
    const int nCh = kPerSplit / 128;

    // split-K: write to private partial slice
    float* Cz = C + (size_t)blockIdx.z * M * N;

    const char* Ab = (const char*)A;
    const char* Wb = (const char*)W;

    auto issue = [&](int j) {
        const int st = j & (NSTG_BIG - 1);
        const uint32_t stA = sb + st * STG_BIG;
        const uint32_t stB = stA + 65536;
        const int kt = k0 + j * 128;
#pragma unroll
        for (int i = 0; i < 16; i++) {
            int c = i * 256 + tid;              // 0..4095
            int r = c >> 4, g = c & 15;
            int half = g >> 3, gg = g & 7;
            cp16(stA + half * 32768 + swz(r, gg * 16),
                 Ab + ((size_t)(row0 + r) * K + kt + g * 8) * 2);
        }
#pragma unroll
        for (int i = 0; i < 8; i++) {
            int c = i * 256 + tid;              // 0..2047
            int r = c >> 4, g = c & 15;
            int half = g >> 3, gg = g & 7;
            cp16(stB + half * 16384 + swz(r, gg * 16),
                 Wb + ((size_t)(col0 + r) * K + kt + g * 8) * 2);
        }
        cp_commit();
    };

    float acc[4][8][4];
#pragma unroll
    for (int i = 0; i < 4; i++)
#pragma unroll
        for (int j = 0; j < 8; j++)
#pragma unroll
            for (int q = 0; q < 4; q++) acc[i][j][q] = 0.f;

    // prologue: fill BOTH stages
    issue(0);
    if (nCh > 1) issue(1);

    const int ra_l = (lane & 15);
    const int ga_l = (lane >> 4) * 16;
    const int rb_l = ((lane >> 4) & 1) * 8 + (lane & 7);
    const int gb_l = ((lane >> 3) & 1) * 16;

    for (int j = 0; j < nCh; j++) {
        if (j + 1 < nCh) cp_wait<1>(); else cp_wait<0>();
        __syncthreads();

        const int st = j & (NSTG_BIG - 1);
        const uint32_t sA = sb + st * STG_BIG;
        const uint32_t sB = sA + 65536;

#pragma unroll
        for (int s = 0; s < 8; s++) {
            const uint32_t hA = sA + (s >> 2) * 32768;
            const uint32_t hB = sB + (s >> 2) * 16384;
            const int so = (s & 3) * 32;
            uint32_t ah[4][4], bh[4][4];
#pragma unroll
            for (int mi = 0; mi < 4; mi++) {
                int r = wm * 64 + mi * 16 + ra_l;
                ldm4(ah[mi], hA + swz(r, so + ga_l));
            }
#pragma unroll
            for (int p = 0; p < 4; p++) {
                int r = wn * 64 + p * 16 + rb_l;
                ldm4(bh[p], hB + swz(r, so + gb_l));
            }
#pragma unroll
            for (int mi = 0; mi < 4; mi++) {
#pragma unroll
                for (int ni = 0; ni < 8; ni++) {
                    mma16816(acc[mi][ni], ah[mi], &bh[ni >> 1][(ni & 1) * 2]);
                }
            }
        }

        if (j + 2 < nCh) {
            __syncthreads();
            issue(j + 2);
        }
    }

    const int er = (lane >> 2);
    const int ec = (lane & 3) * 2;
#pragma unroll
    for (int mi = 0; mi < 4; mi++) {
#pragma unroll
        for (int ni = 0; ni < 8; ni++) {
            int r = row0 + wm * 64 + mi * 16 + er;
            int c = col0 + wn * 64 + ni * 8 + ec;
            float2 p0 = {acc[mi][ni][0], acc[mi][ni][1]};
            float2 p1 = {acc[mi][ni][2], acc[mi][ni][3]};
            *(float2*)(Cz + (size_t)r * N + c)       = p0;
            *(float2*)(Cz + (size_t)(r + 8) * N + c) = p1;
        }
    }
}

// ================= reduce two split-K partials -> output =================
__global__ void reduce2(const float* __restrict__ p, float* __restrict__ out, int n)
{
    int idx = blockIdx.x * blockDim.x + threadIdx.x;   // over n/4
    if (idx >= (n >> 2)) return;
    float4 a = *(const float4*)(p + (size_t)idx * 4);
    float4 b = *(const float4*)(p + (size_t)n + (size_t)idx * 4);
    float4 r = {a.x + b.x, a.y + b.y, a.z + b.z, a.w + b.w};
    *(float4*)(out + (size_t)idx * 4) = r;
}

// ================= converts =================
__global__ void convert_fp16_2(const float* __restrict__ X1, __half* __restrict__ Y1, int n1,
                               const float* __restrict__ X2, __half* __restrict__ Y2, int n2)
{
    int idx = blockIdx.x * blockDim.x + threadIdx.x;
    int tot = (n1 + n2) >> 3;
    if (idx >= tot) return;
    const float* X; __half* Y; size_t off;
    if (idx < (n1 >> 3)) { X = X1; Y = Y1; off = (size_t)idx * 8; }
    else { X = X2; Y = Y2; off = (size_t)(idx - (n1 >> 3)) * 8; }
    float4 v0 = *(const float4*)(X + off);
    float4 v1 = *(const float4*)(X + off + 4);
    union { uint4 u; __half h[8]; } o;
    o.h[0] = __float2half_rn(v0.x); o.h[1] = __float2half_rn(v0.y);
    o.h[2] = __float2half_rn(v0.z); o.h[3] = __float2half_rn(v0.w);
    o.h[4] = __float2half_rn(v1.x); o.h[5] = __float2half_rn(v1.y);
    o.h[6] = __float2half_rn(v1.z); o.h[7] = __float2half_rn(v1.w);
    *(uint4*)(Y + off) = o.u;
}

__global__ void build_wbcd(const float* __restrict__ wB, const float* __restrict__ wC,
                           const float* __restrict__ wD1, __half* __restrict__ Y)
{
    int idx = blockIdx.x * blockDim.x + threadIdx.x;
    if (idx >= (N_BCT * D_MODEL) >> 3) return;
    int r = idx / (D_MODEL >> 3);
    int k = (idx % (D_MODEL >> 3)) << 3;
    const float* src = nullptr;
    if (r < 16)       src = wB  + (size_t)r * D_MODEL + k;
    else if (r < 32)  src = wC  + (size_t)(r - 16) * D_MODEL + k;
    else if (r < 160) src = wD1 + (size_t)(r - 32) * D_MODEL + k;
    union { uint4 u; __half h[8]; } o;
    if (src) {
        float4 v0 = *(const float4*)src;
        float4 v1 = *(const float4*)(src + 4);
        o.h[0]=__float2half_rn(v0.x); o.h[1]=__float2half_rn(v0.y);
        o.h[2]=__float2half_rn(v0.z); o.h[3]=__float2half_rn(v0.w);
        o.h[4]=__float2half_rn(v1.x); o.h[5]=__float2half_rn(v1.y);
        o.h[6]=__float2half_rn(v1.z); o.h[7]=__float2half_rn(v1.w);
    } else {
        o.u = make_uint4(0,0,0,0);
    }
    *(uint4*)(Y + (size_t)r * D_MODEL + k) = o.u;
}

__global__ void extract_t(const float* __restrict__ tall, __half* __restrict__ Y)
{
    int idx = blockIdx.x * blockDim.x + threadIdx.x;
    if (idx >= (M_ROWS * D_DISCR) >> 2) return;
    int r = idx / (D_DISCR >> 2);
    int c = (idx % (D_DISCR >> 2)) << 2;
    float4 v = *(const float4*)(tall + (size_t)r * N_BCT + 32 + c);
    union { uint2 u; __half h[4]; } o;
    o.h[0]=__float2half_rn(v.x); o.h[1]=__float2half_rn(v.y);
    o.h[2]=__float2half_rn(v.z); o.h[3]=__float2half_rn(v.w);
    *(uint2*)(Y + (size_t)r * D_DISCR + c) = o.u;
}

// ------ depthwise causal conv (ker=4) + bias + SiLU -> a_h fp16 ------
__global__ void conv_silu_kernel(const float* __restrict__ ab,
                                 const float* __restrict__ cw,
                                 const float* __restrict__ cb,
                                 __half* __restrict__ a_h)
{
    int idx = blockIdx.x * blockDim.x + threadIdx.x;
    if (idx >= B_SZ * L_SEQ * D_MODEL) return;
    int d = idx & (D_MODEL - 1);
    int l = (idx >> 11) & (L_SEQ - 1);
    int b = idx >> 21;

    float w0 = cw[d*4+0], w1 = cw[d*4+1], w2 = cw[d*4+2], w3 = cw[d*4+3];
    const size_t rowBase = ((size_t)b * L_SEQ) * (2*D_MODEL);
    float s = cb[d];
    if (l >= 3) s += w0 * ab[rowBase + (size_t)(l-3)*(2*D_MODEL) + d];
    if (l >= 2) s += w1 * ab[rowBase + (size_t)(l-2)*(2*D_MODEL) + d];
    if (l >= 1) s += w2 * ab[rowBase + (size_t)(l-1)*(2*D_MODEL) + d];
    s += w3 * ab[rowBase + (size_t)l*(2*D_MODEL) + d];
    float v = s / (1.f + expf(-s));
    a_h[idx] = __float2half_rn(v);
}

// ================= chunked scan =================
__global__ __launch_bounds__(128)
void scan_phase1(const float* __restrict__ delta,
                 const __half* __restrict__ a_h,
                 const float* __restrict__ tall,
                 const float* __restrict__ A_param,
                 float* __restrict__ Pb,
                 float* __restrict__ hendb)
{
    int gid = blockIdx.x * blockDim.x + threadIdx.x;
    int ch = gid & (NCHAN - 1);
    int chunk = gid >> 12;
    int b = ch >> 11;
    int d = ch & (D_MODEL - 1);

    float expA[D_STATE];
#pragma unroll
    for (int s = 0; s < D_STATE; s++) expA[s] = expf(-A_param[(size_t)d * D_STATE + s]);

    float h[D_STATE], P[D_STATE];
#pragma unroll
    for (int s = 0; s < D_STATE; s++) { h[s] = 0.f; P[s] = 1.f; }

    const int l0 = chunk * LCHUNK;
    for (int l = l0; l < l0 + LCHUNK; l++) {
        const size_t row = (size_t)b * L_SEQ + l;
        float dlt = delta[row * D_MODEL + d];
        float av  = __half2float(a_h[row * D_MODEL + d]);
        const float4* Bp = (const float4*)(tall + row * N_BCT);
        float4 B0 = Bp[0], B1 = Bp[1], B2 = Bp[2], B3 = Bp[3];
        float Bv[16] = {B0.x,B0.y,B0.z,B0.w, B1.x,B1.y,B1.z,B1.w,
                        B2.x,B2.y,B2.z,B2.w, B3.x,B3.y,B3.z,B3.w};
        float xc = dlt * av;
#pragma unroll
        for (int s = 0; s < D_STATE; s++) {
            float Ab = expA[s] * dlt;
            h[s] = fmaf(Ab, h[s], Bv[s] * xc);
            P[s] *= Ab;
        }
    }
    float4* Pd = (float4*)(Pb    + ((size_t)chunk * NCHAN + ch) * D_STATE);
    float4* Hd = (float4*)(hendb + ((size_t)chunk * NCHAN + ch) * D_STATE);
#pragma unroll
    for (int q = 0; q < 4; q++) {
        Pd[q] = make_float4(P[q*4], P[q*4+1], P[q*4+2], P[q*4+3]);
        Hd[q] = make_float4(h[q*4], h[q*4+1], h[q*4+2], h[q*4+3]);
    }
}

__global__ __launch_bounds__(128)
void scan_phase2(const float* __restrict__ Pb,
                 const float* __restrict__ hendb,
                 float* __restrict__ hstartb)
{
    int ch = blockIdx.x * blockDim.x + threadIdx.x;
    if (ch >= NCHAN) return;
    float hs[D_STATE];
#pragma unroll
    for (int s = 0; s < D_STATE; s++) hs[s] = 0.f;
    for (int c = 0; c < NCHUNK; c++) {
        float4* Hs = (float4*)(hstartb + ((size_t)c * NCHAN + ch) * D_STATE);
#pragma unroll
        for (int q = 0; q < 4; q++)
            Hs[q] = make_float4(hs[q*4], hs[q*4+1], hs[q*4+2], hs[q*4+3]);
        const float4* Pd = (const float4*)(Pb    + ((size_t)c * NCHAN + ch) * D_STATE);
        const float4* He = (const float4*)(hendb + ((size_t)c * NCHAN + ch) * D_STATE);
#pragma unroll
        for (int q = 0; q < 4; q++) {
            float4 p = Pd[q], e = He[q];
            hs[q*4+0] = fmaf(p.x, hs[q*4+0], e.x);
            hs[q*4+1] = fmaf(p.y, hs[q*4+1], e.y);
            hs[q*4+2] = fmaf(p.z, hs[q*4+2], e.z);
            hs[q*4+3] = fmaf(p.w, hs[q*4+3], e.w);
        }
    }
}

__global__ __launch_bounds__(128)
void scan_phase3(const float* __restrict__ delta,
                 const __half* __restrict__ a_h,
                 const float* __restrict__ ab,
                 const float* __restrict__ tall,
                 const float* __restrict__ A_param,
                 const float* __restrict__ D_param,
                 const float* __restrict__ hstartb,
                 __half* __restrict__ y_h)
{
    int gid = blockIdx.x * blockDim.x + threadIdx.x;
    int ch = gid & (NCHAN - 1);
    int chunk = gid >> 12;
    int b = ch >> 11;
    int d = ch & (D_MODEL - 1);

    float expA[D_STATE];
#pragma unroll
    for (int s = 0; s < D_STATE; s++) expA[s] = expf(-A_param[(size_t)d * D_STATE + s]);
    const float Dp = D_param[d];

    float h[D_STATE];
    const float4* Hs = (const float4*)(hstartb + ((size_t)chunk * NCHAN + ch) * D_STATE);
#pragma unroll
    for (int q = 0; q < 4; q++) {
        float4 v = Hs[q];
        h[q*4+0] = v.x; h[q*4+1] = v.y; h[q*4+2] = v.z; h[q*4+3] = v.w;
    }

    const int l0 = chunk * LCHUNK;
    for (int l = l0; l < l0 + LCHUNK; l++) {
        const size_t row = (size_t)b * L_SEQ + l;
        float dlt = delta[row * D_MODEL + d];
        float av  = __half2float(a_h[row * D_MODEL + d]);
        float gt  = ab[row * (2*D_MODEL) + D_MODEL + d];
        const float4* Bp = (const float4*)(tall + row * N_BCT);
        const float4* Cp = (const float4*)(tall + row * N_BCT + 16);
        float4 B0 = Bp[0], B1 = Bp[1], B2 = Bp[2], B3 = Bp[3];
        float4 C0 = Cp[0], C1 = Cp[1], C2 = Cp[2], C3 = Cp[3];
        float Bv[16] = {B0.x,B0.y,B0.z,B0.w, B1.x,B1.y,B1.z,B1.w,
                        B2.x,B2.y,B2.z,B2.w, B3.x,B3.y,B3.z,B3.w};
        float Cv[16] = {C0.x,C0.y,C0.z,C0.w, C1.x,C1.y,C1.z,C1.w,
                        C2.x,C2.y,C2.z,C2.w, C3.x,C3.y,C3.z,C3.w};
        float xc = dlt * av;
        float acc0 = 0.f, acc1 = 0.f;
#pragma unroll
        for (int s = 0; s < D_STATE; s += 2) {
            float Ab0 = expA[s]   * dlt;
            float Ab1 = expA[s+1] * dlt;
            h[s]   = fmaf(Ab0, h[s],   Bv[s]   * xc);
            h[s+1] = fmaf(Ab1, h[s+1], Bv[s+1] * xc);
            acc0   = fmaf(h[s],   Cv[s],   acc0);
            acc1   = fmaf(h[s+1], Cv[s+1], acc1);
        }
        float silu_g = gt / (1.f + expf(-gt));
        float yv = (acc0 + acc1 + Dp * av) * silu_g;
        y_h[row * D_MODEL + d] = __float2half_rn(yv);
    }
}

// ---------------- launch ----------------
extern "C" void kernel_launch(void* const* d_in, const int* in_sizes, int n_in,
                              void* d_out, int out_size)
{
    const float* seq     = (const float*)d_in[0];
    const float* w_in    = (const float*)d_in[1];
    const float* w_out   = (const float*)d_in[2];
    const float* w_B     = (const float*)d_in[3];
    const float* w_C     = (const float*)d_in[4];
    const float* w_D1    = (const float*)d_in[5];
    const float* w_D2    = (const float*)d_in[6];
    const float* conv_w  = (const float*)d_in[7];
    const float* conv_b  = (const float*)d_in[8];
    const float* A_param = (const float*)d_in[9];
    const float* D_param = (const float*)d_in[10];
    float* out = (float*)d_out;

    float *ab_p, *tall_p, *delta_p, *P_p, *hend_p, *hstart_p, *outp_p;
    __half *seq_h, *win_h, *a_h, *wbcd_h, *wd2_h, *t_h, *wout_h, *y_h;
    cudaGetSymbolAddress((void**)&ab_p,    g_ab);
    cudaGetSymbolAddress((void**)&tall_p,  g_tall);
    cudaGetSymbolAddress((void**)&delta_p, g_delta);
    cudaGetSymbolAddress((void**)&P_p,     g_P);
    cudaGetSymbolAddress((void**)&hend_p,  g_hend);
    cudaGetSymbolAddress((void**)&hstart_p,g_hstart);
    cudaGetSymbolAddress((void**)&outp_p,  g_outp);
    cudaGetSymbolAddress((void**)&seq_h,   g_seq_h);
    cudaGetSymbolAddress((void**)&win_h,   g_win_h);
    cudaGetSymbolAddress((void**)&a_h,     g_a_h);
    cudaGetSymbolAddress((void**)&wbcd_h,  g_wbcd_h);
    cudaGetSymbolAddress((void**)&wd2_h,   g_wd2_h);
    cudaGetSymbolAddress((void**)&t_h,     g_t_h);
    cudaGetSymbolAddress((void**)&wout_h,  g_wout_h);
    cudaGetSymbolAddress((void**)&y_h,     g_y_h);

    cudaFuncSetAttribute(mma_gemm<0>, cudaFuncAttributeMaxDynamicSharedMemorySize, GSMEM);
    cudaFuncSetAttribute(mma_gemm<1>, cudaFuncAttributeMaxDynamicSharedMemorySize, GSMEM);
    cudaFuncSetAttribute(mma_gemm<2>, cudaFuncAttributeMaxDynamicSharedMemorySize, GSMEM);
    cudaFuncSetAttribute(mma_gemm_big, cudaFuncAttributeMaxDynamicSharedMemorySize, GSMEM_BIG);

    static cudaStream_t s2 = nullptr;
    static cudaEvent_t evFork = nullptr, evJoin = nullptr;
    if (s2 == nullptr) {
        cudaStreamCreateWithFlags(&s2, cudaStreamNonBlocking);
        cudaEventCreateWithFlags(&evFork, cudaEventDisableTiming);
        cudaEventCreateWithFlags(&evJoin, cudaEventDisableTiming);
    }

    // fork: side stream converts weights not needed until step 3+
    cudaEventRecord(evFork, 0);
    cudaStreamWaitEvent(s2, evFork, 0);
    convert_fp16_2<<<(((D_MODEL*D_DISCR + D_IN*D_MODEL) >> 3) + 255)/256, 256, 0, s2>>>(
        w_D2, wd2_h, D_MODEL * D_DISCR, w_out, wout_h, D_IN * D_MODEL);
    build_wbcd<<<((N_BCT*D_MODEL >> 3) + 255)/256, 256, 0, s2>>>(w_B, w_C, w_D1, wbcd_h);
    cudaEventRecord(evJoin, s2);

    // main stream: converts needed immediately (fused into one launch)
    convert_fp16_2<<<(((M_ROWS*D_IN + 2*D_MODEL*D_IN) >> 3) + 255)/256, 256>>>(
        seq, seq_h, M_ROWS * D_IN, w_in, win_h, 2*D_MODEL * D_IN);

    // 1) in_proj: ab = seq @ w_in^T   (2048 x 4096, K=1024) — big tile
    {
        dim3 grid(M_ROWS/256, (2*D_MODEL)/128, 1);
        mma_gemm_big<<<grid, 256, GSMEM_BIG>>>(M_ROWS, 2*D_MODEL, D_IN,
                                               seq_h, win_h, ab_p, D_IN);
    }
    // 2) depthwise conv + bias + silu -> a_h fp16
    {
        int n = B_SZ * L_SEQ * D_MODEL;
        conv_silu_kernel<<<(n + 255)/256, 256>>>(ab_p, conv_w, conv_b, a_h);
    }
    cudaMemsetAsync(tall_p, 0, (size_t)M_ROWS * N_BCT * sizeof(float));

    cudaStreamWaitEvent(0, evJoin, 0);

    // 3) fused BCt: t_all = a @ [w_B|w_C|w_D1|0]^T  (2048 x 256, K=2048), split-K=8
    {
        dim3 grid(M_ROWS/128, N_BCT/128, 8);
        mma_gemm<2><<<grid, 256, GSMEM>>>(M_ROWS, N_BCT, D_MODEL,
                                          a_h, wbcd_h, tall_p, nullptr, D_MODEL/8);
    }
    // 4) t -> fp16
    extract_t<<<((M_ROWS*D_DISCR >> 2) + 255)/256, 256>>>(tall_p, t_h);
    // 5) delta = softplus(D_param + t @ w_D2^T)   (2048 x 2048, K=128)
    {
        dim3 grid(M_ROWS/128, D_MODEL/128, 1);
        mma_gemm<1><<<grid, 256, GSMEM>>>(M_ROWS, D_MODEL, D_DISCR,
                                          t_h, wd2_h, delta_p, D_param, D_DISCR);
    }
    // 6) chunked scan
    scan_phase1<<<(NCHAN*NCHUNK)/128, 128>>>(delta_p, a_h, tall_p, A_param, P_p, hend_p);
    scan_phase2<<<NCHAN/128, 128>>>(P_p, hend_p, hstart_p);
    scan_phase3<<<(NCHAN*NCHUNK)/128, 128>>>(delta_p, a_h, ab_p, tall_p,
                                             A_param, D_param, hstart_p, y_h);
    // 7) out = y @ w_out^T  (2048 x 1024, K=2048) — big tile split-K=2 -> partials
    {
        dim3 grid(M_ROWS/256, D_IN/128, 2);
        mma_gemm_big<<<grid, 256, GSMEM_BIG>>>(M_ROWS, D_IN, D_MODEL,
                                               y_h, wout_h, outp_p, D_MODEL/2);
    }
    // 8) out = p0 + p1
    {
        int n = M_ROWS * D_IN;
        reduce2<<<((n >> 2) + 255)/256, 256>>>(outp_p, out, n);
    }
}

// round 16
// speedup vs baseline: 1.0682x; 1.0496x over previous
#include <cuda_runtime.h>
#include <cuda_fp16.h>
#include <cstdint>
#include <math.h>

// Problem constants
#define B_SZ 2
#define L_SEQ 1024
#define D_IN 1024
#define D_MODEL 2048
#define D_STATE 16
#define D_DISCR 128
#define KER 4
#define M_ROWS (B_SZ * L_SEQ)          // 2048
#define N_BCT 256                      // padded: 16 B + 16 C + 128 D1 + 96 zero
#define NCHUNK 16
#define LCHUNK (L_SEQ / NCHUNK)        // 64
#define NCHAN (B_SZ * D_MODEL)         // 4096

// ---------------- scratch (device globals; no allocation) ----------------
__device__ float g_ab[(size_t)M_ROWS * 2 * D_MODEL];      // in_proj out [2048,4096]
__device__ float g_tall[(size_t)M_ROWS * N_BCT];          // [Bm|Cm|t|pad] fp32
__device__ float g_P[(size_t)NCHUNK * NCHAN * D_STATE];
__device__ float g_hend[(size_t)NCHUNK * NCHAN * D_STATE];
__device__ float g_hstart[(size_t)NCHUNK * NCHAN * D_STATE];
__device__ float g_outp[(size_t)2 * M_ROWS * D_IN];       // out_proj split-K partials
// fp16 operands
__device__ __half g_delta_h[(size_t)M_ROWS * D_MODEL];    // softplus output, fp16
__device__ __half g_seq_h [(size_t)M_ROWS * D_IN];
__device__ __half g_win_h [(size_t)(2*D_MODEL) * D_IN];
__device__ __half g_a_h   [(size_t)M_ROWS * D_MODEL];
__device__ __half g_wbcd_h[(size_t)N_BCT * D_MODEL];
__device__ __half g_wd2_h [(size_t)D_MODEL * D_DISCR];
__device__ __half g_t_h   [(size_t)M_ROWS * D_DISCR];
__device__ __half g_wout_h[(size_t)D_IN * D_MODEL];
__device__ __half g_y_h   [(size_t)M_ROWS * D_MODEL];

// ================= helpers =================
__device__ __forceinline__ uint32_t smem_u32(const void* p) {
    uint32_t a;
    asm("{ .reg .u64 t; cvta.to.shared.u64 t, %1; cvt.u32.u64 %0, t; }" : "=r"(a) : "l"(p));
    return a;
}
__device__ __forceinline__ void ldm4(uint32_t* r, uint32_t addr) {
    asm volatile("ldmatrix.sync.aligned.m8n8.x4.shared.b16 {%0,%1,%2,%3}, [%4];"
                 : "=r"(r[0]), "=r"(r[1]), "=r"(r[2]), "=r"(r[3]) : "r"(addr));
}
__device__ __forceinline__ void mma16816(float* c, const uint32_t* a, const uint32_t* b) {
    asm volatile("mma.sync.aligned.m16n8k16.row.col.f32.f16.f16.f32 "
                 "{%0,%1,%2,%3}, {%4,%5,%6,%7}, {%8,%9}, {%0,%1,%2,%3};"
                 : "+f"(c[0]), "+f"(c[1]), "+f"(c[2]), "+f"(c[3])
                 : "r"(a[0]), "r"(a[1]), "r"(a[2]), "r"(a[3]), "r"(b[0]), "r"(b[1]));
}
__device__ __forceinline__ void cp16(uint32_t dst, const void* src) {
    asm volatile("cp.async.cg.shared.global [%0], [%1], 16;" :: "r"(dst), "l"(src));
}
__device__ __forceinline__ void cp_commit() {
    asm volatile("cp.async.commit_group;" ::: "memory");
}
template<int N>
__device__ __forceinline__ void cp_wait() {
    asm volatile("cp.async.wait_group %0;" :: "n"(N) : "memory");
}
__device__ __forceinline__ uint32_t swz(int r, int byteCol) {
    uint32_t off = (uint32_t)(r * 128 + byteCol);
    return off ^ (((uint32_t)r & 7u) << 4);
}

// ================= pipelined fp16 HMMA NT GEMM (128x128, BK=64) =============
// EPI: 0 plain fp32 store, 1 softplus->fp32, 2 atomicAdd (split-K),
//      3 softplus->fp16 store (C reinterpreted as __half*).
#define STG 32768
#define NSTG 3
#define GSMEM (NSTG * STG)   // 96 KB

template<int EPI>
__global__ __launch_bounds__(256, 2)
void mma_gemm(int M, int N, int K,
              const __half* __restrict__ A,
              const __half* __restrict__ W,
              float* __restrict__ C,
              const float* __restrict__ bias,
              int kPerSplit)
{
    extern __shared__ char smem[];
    const uint32_t sb = smem_u32(smem);
    const int tid = threadIdx.x;
    const int wid = tid >> 5, lane = tid & 31;
    const int wm = wid & 1, wn = wid >> 1;          // 2 x 4 warp grid
    const int row0 = blockIdx.x * 128;
    const int col0 = blockIdx.y * 128;
    const int k0 = blockIdx.z * kPerSplit;
    const int nCh = kPerSplit / 64;

    const char* Ab = (const char*)A;
    const char* Wb = (const char*)W;

    auto issue = [&](int j) {
        const int st = j % NSTG;
        const uint32_t stA = sb + st * STG;
        const uint32_t stB = stA + 16384;
        const int kt = k0 + j * 64;
#pragma unroll
        for (int i = 0; i < 4; i++) {
            int c = i * 256 + tid;
            int r = c >> 3, g = c & 7;
            cp16(stA + swz(r, g * 16),
                 Ab + ((size_t)(row0 + r) * K + kt) * 2 + g * 16);
        }
#pragma unroll
        for (int i = 0; i < 4; i++) {
            int c = i * 256 + tid;
            int r = c >> 3, g = c & 7;
            cp16(stB + swz(r, g * 16),
                 Wb + ((size_t)(col0 + r) * K + kt) * 2 + g * 16);
        }
        cp_commit();
    };

    float acc[4][4][4];
#pragma unroll
    for (int i = 0; i < 4; i++)
#pragma unroll
        for (int j = 0; j < 4; j++)
#pragma unroll
            for (int q = 0; q < 4; q++) acc[i][j][q] = 0.f;

    const int pre = (nCh < NSTG - 1) ? nCh : (NSTG - 1);
    for (int j = 0; j < pre; j++) issue(j);

    const int ra_l = (lane & 15);
    const int ga_l = (lane >> 4) * 16;
    const int rb_l = ((lane >> 4) & 1) * 8 + (lane & 7);
    const int gb_l = ((lane >> 3) & 1) * 16;

    for (int j = 0; j < nCh; j++) {
        int newer = nCh - 1 - j; if (newer > NSTG - 2) newer = NSTG - 2;
        if (newer >= 1) cp_wait<1>(); else cp_wait<0>();
        __syncthreads();

        if (j + NSTG - 1 < nCh) issue(j + NSTG - 1);

        const int st = j % NSTG;
        const uint32_t sA = sb + st * STG;
        const uint32_t sB = sA + 16384;

#pragma unroll
        for (int s = 0; s < 4; s++) {
            uint32_t ah[4][4], bh[2][4];
#pragma unroll
            for (int mi = 0; mi < 4; mi++) {
                int r = wm * 64 + mi * 16 + ra_l;
                ldm4(ah[mi], sA + swz(r, s * 32 + ga_l));
            }
#pragma unroll
            for (int p = 0; p < 2; p++) {
                int r = wn * 32 + p * 16 + rb_l;
                ldm4(bh[p], sB + swz(r, s * 32 + gb_l));
            }
#pragma unroll
            for (int mi = 0; mi < 4; mi++) {
#pragma unroll
                for (int ni = 0; ni < 4; ni++) {
                    mma16816(acc[mi][ni], ah[mi], &bh[ni >> 1][(ni & 1) * 2]);
                }
            }
        }
    }

    const int er = (lane >> 2);
    const int ec = (lane & 3) * 2;
#pragma unroll
    for (int mi = 0; mi < 4; mi++) {
#pragma unroll
        for (int ni = 0; ni < 4; ni++) {
            int r = row0 + wm * 64 + mi * 16 + er;
            int c = col0 + wn * 32 + ni * 8 + ec;
            float v0 = acc[mi][ni][0], v1 = acc[mi][ni][1];
            float v2 = acc[mi][ni][2], v3 = acc[mi][ni][3];
            if (EPI == 1 || EPI == 3) {
                float b0 = bias[c], b1 = bias[c + 1];
                float x;
                x = b0 + v0; v0 = (x > 20.f) ? x : log1pf(expf(x));
                x = b1 + v1; v1 = (x > 20.f) ? x : log1pf(expf(x));
                x = b0 + v2; v2 = (x > 20.f) ? x : log1pf(expf(x));
                x = b1 + v3; v3 = (x > 20.f) ? x : log1pf(expf(x));
            }
            if (EPI == 3) {
                __half* Ch = (__half*)C;
                *(__half2*)(Ch + (size_t)r * N + c)       = __floats2half2_rn(v0, v1);
                *(__half2*)(Ch + (size_t)(r + 8) * N + c) = __floats2half2_rn(v2, v3);
            } else if (EPI == 2) {
                atomicAdd(C + (size_t)r * N + c,           v0);
                atomicAdd(C + (size_t)r * N + c + 1,       v1);
                atomicAdd(C + (size_t)(r + 8) * N + c,     v2);
                atomicAdd(C + (size_t)(r + 8) * N + c + 1, v3);
            } else {
                float2 p0 = {v0, v1}, p1 = {v2, v3};
                *(float2*)(C + (size_t)r * N + c)       = p0;
                *(float2*)(C + (size_t)(r + 8) * N + c) = p1;
            }
        }
    }
}

// ============ big-tile GEMM: 256x128, BK=128, 2 stages, optional split-K ====
#define STG_BIG 98304            // 96 KB
#define NSTG_BIG 2
#define GSMEM_BIG (NSTG_BIG * STG_BIG)  // 192 KB

__global__ __launch_bounds__(256, 1)
void mma_gemm_big(int M, int N, int K,
                  const __half* __restrict__ A,
                  const __half* __restrict__ W,
                  float* __restrict__ C,
                  int kPerSplit)
{
    extern __shared__ char smem[];
    const uint32_t sb = smem_u32(smem);
    const int tid = threadIdx.x;
    const int wid = tid >> 5, lane = tid & 31;
    const int wm = wid & 3, wn = wid >> 2;          // 4 x 2 warp grid
    const int row0 = blockIdx.x * 256;
    const int col0 = blockIdx.y * 128;
    const int k0 = blockIdx.z * kPerSplit;
    const int nCh = kPerSplit / 128;

    float* Cz = C + (size_t)blockIdx.z * M * N;

    const char* Ab = (const char*)A;
    const char* Wb = (const char*)W;

    auto issue = [&](int j) {
        const int st = j & (NSTG_BIG - 1);
        const uint32_t stA = sb + st * STG_BIG;
        const uint32_t stB = stA + 65536;
        const int kt = k0 + j * 128;
#pragma unroll
        for (int i = 0; i < 16; i++) {
            int c = i * 256 + tid;
            int r = c >> 4, g = c & 15;
            int half = g >> 3, gg = g & 7;
            cp16(stA + half * 32768 + swz(r, gg * 16),
                 Ab + ((size_t)(row0 + r) * K + kt + g * 8) * 2);
        }
#pragma unroll
        for (int i = 0; i < 8; i++) {
            int c = i * 256 + tid;
            int r = c >> 4, g = c & 15;
            int half = g >> 3, gg = g & 7;
            cp16(stB + half * 16384 + swz(r, gg * 16),
                 Wb + ((size_t)(col0 + r) * K + kt + g * 8) * 2);
        }
        cp_commit();
    };

    float acc[4][8][4];
#pragma unroll
    for (int i = 0; i < 4; i++)
#pragma unroll
        for (int j = 0; j < 8; j++)
#pragma unroll
            for (int q = 0; q < 4; q++) acc[i][j][q] = 0.f;

    issue(0);
    if (nCh > 1) issue(1);

    const int ra_l = (lane & 15);
    const int ga_l = (lane >> 4) * 16;
    const int rb_l = ((lane >> 4) & 1) * 8 + (lane & 7);
    const int gb_l = ((lane >> 3) & 1) * 16;

    for (int j = 0; j < nCh; j++) {
        if (j + 1 < nCh) cp_wait<1>(); else cp_wait<0>();
        __syncthreads();

        const int st = j & (NSTG_BIG - 1);
        const uint32_t sA = sb + st * STG_BIG;
        const uint32_t sB = sA + 65536;

#pragma unroll
        for (int s = 0; s < 8; s++) {
            const uint32_t hA = sA + (s >> 2) * 32768;
            const uint32_t hB = sB + (s >> 2) * 16384;
            const int so = (s & 3) * 32;
            uint32_t ah[4][4], bh[4][4];
#pragma unroll
            for (int mi = 0; mi < 4; mi++) {
                int r = wm * 64 + mi * 16 + ra_l;
                ldm4(ah[mi], hA + swz(r, so + ga_l));
            }
#pragma unroll
            for (int p = 0; p < 4; p++) {
                int r = wn * 64 + p * 16 + rb_l;
                ldm4(bh[p], hB + swz(r, so + gb_l));
            }
#pragma unroll
            for (int mi = 0; mi < 4; mi++) {
#pragma unroll
                for (int ni = 0; ni < 8; ni++) {
                    mma16816(acc[mi][ni], ah[mi], &bh[ni >> 1][(ni & 1) * 2]);
                }
            }
        }

        if (j + 2 < nCh) {
            __syncthreads();
            issue(j + 2);
        }
    }

    const int er = (lane >> 2);
    const int ec = (lane & 3) * 2;
#pragma unroll
    for (int mi = 0; mi < 4; mi++) {
#pragma unroll
        for (int ni = 0; ni < 8; ni++) {
            int r = row0 + wm * 64 + mi * 16 + er;
            int c = col0 + wn * 64 + ni * 8 + ec;
            float2 p0 = {acc[mi][ni][0], acc[mi][ni][1]};
            float2 p1 = {acc[mi][ni][2], acc[mi][ni][3]};
            *(float2*)(Cz + (size_t)r * N + c)       = p0;
            *(float2*)(Cz + (size_t)(r + 8) * N + c) = p1;
        }
    }
}

// ================= reduce two split-K partials -> output =================
__global__ void reduce2(const float* __restrict__ p, float* __restrict__ out, int n)
{
    int idx = blockIdx.x * blockDim.x + threadIdx.x;
    if (idx >= (n >> 2)) return;
    float4 a = *(const float4*)(p + (size_t)idx * 4);
    float4 b = *(const float4*)(p + (size_t)n + (size_t)idx * 4);
    float4 r = {a.x + b.x, a.y + b.y, a.z + b.z, a.w + b.w};
    *(float4*)(out + (size_t)idx * 4) = r;
}

// ================= converts =================
__global__ void convert_fp16_2(const float* __restrict__ X1, __half* __restrict__ Y1, int n1,
                               const float* __restrict__ X2, __half* __restrict__ Y2, int n2)
{
    int idx = blockIdx.x * blockDim.x + threadIdx.x;
    int tot = (n1 + n2) >> 3;
    if (idx >= tot) return;
    const float* X; __half* Y; size_t off;
    if (idx < (n1 >> 3)) { X = X1; Y = Y1; off = (size_t)idx * 8; }
    else { X = X2; Y = Y2; off = (size_t)(idx - (n1 >> 3)) * 8; }
    float4 v0 = *(const float4*)(X + off);
    float4 v1 = *(const float4*)(X + off + 4);
    union { uint4 u; __half h[8]; } o;
    o.h[0] = __float2half_rn(v0.x); o.h[1] = __float2half_rn(v0.y);
    o.h[2] = __float2half_rn(v0.z); o.h[3] = __float2half_rn(v0.w);
    o.h[4] = __float2half_rn(v1.x); o.h[5] = __float2half_rn(v1.y);
    o.h[6] = __float2half_rn(v1.z); o.h[7] = __float2half_rn(v1.w);
    *(uint4*)(Y + off) = o.u;
}

__global__ void build_wbcd(const float* __restrict__ wB, const float* __restrict__ wC,
                           const float* __restrict__ wD1, __half* __restrict__ Y)
{
    int idx = blockIdx.x * blockDim.x + threadIdx.x;
    if (idx >= (N_BCT * D_MODEL) >> 3) return;
    int r = idx / (D_MODEL >> 3);
    int k = (idx % (D_MODEL >> 3)) << 3;
    const float* src = nullptr;
    if (r < 16)       src = wB  + (size_t)r * D_MODEL + k;
    else if (r < 32)  src = wC  + (size_t)(r - 16) * D_MODEL + k;
    else if (r < 160) src = wD1 + (size_t)(r - 32) * D_MODEL + k;
    union { uint4 u; __half h[8]; } o;
    if (src) {
        float4 v0 = *(const float4*)src;
        float4 v1 = *(const float4*)(src + 4);
        o.h[0]=__float2half_rn(v0.x); o.h[1]=__float2half_rn(v0.y);
        o.h[2]=__float2half_rn(v0.z); o.h[3]=__float2half_rn(v0.w);
        o.h[4]=__float2half_rn(v1.x); o.h[5]=__float2half_rn(v1.y);
        o.h[6]=__float2half_rn(v1.z); o.h[7]=__float2half_rn(v1.w);
    } else {
        o.u = make_uint4(0,0,0,0);
    }
    *(uint4*)(Y + (size_t)r * D_MODEL + k) = o.u;
}

__global__ void extract_t(const float* __restrict__ tall, __half* __restrict__ Y)
{
    int idx = blockIdx.x * blockDim.x + threadIdx.x;
    if (idx >= (M_ROWS * D_DISCR) >> 2) return;
    int r = idx / (D_DISCR >> 2);
    int c = (idx % (D_DISCR >> 2)) << 2;
    float4 v = *(const float4*)(tall + (size_t)r * N_BCT + 32 + c);
    union { uint2 u; __half h[4]; } o;
    o.h[0]=__float2half_rn(v.x); o.h[1]=__float2half_rn(v.y);
    o.h[2]=__float2half_rn(v.z); o.h[3]=__float2half_rn(v.w);
    *(uint2*)(Y + (size_t)r * D_DISCR + c) = o.u;
}

// ------ depthwise causal conv: register-rolling window, 8 l per thread ------
__global__ void conv_silu_kernel(const float* __restrict__ ab,
                                 const float* __restrict__ cw,
                                 const float* __restrict__ cb,
                                 __half* __restrict__ a_h)
{
    int idx = blockIdx.x * blockDim.x + threadIdx.x;   // over NCHAN * L/8
    if (idx >= (B_SZ * L_SEQ * D_MODEL) / 8) return;
    int d   = idx & (D_MODEL - 1);
    int blk = idx >> 11;                // b * (L/8) + lblk
    int lblk = blk & (L_SEQ / 8 - 1);
    int b    = blk >> 7;                // L/8 = 128
    int l0   = lblk * 8;

    float w0 = cw[d*4+0], w1 = cw[d*4+1], w2 = cw[d*4+2], w3 = cw[d*4+3];
    float bias = cb[d];
    const float* col = ab + ((size_t)b * L_SEQ) * (2*D_MODEL) + d;

    float x0 = (l0 >= 3) ? col[(size_t)(l0-3) * (2*D_MODEL)] : 0.f;
    float x1 = (l0 >= 2) ? col[(size_t)(l0-2) * (2*D_MODEL)] : 0.f;
    float x2 = (l0 >= 1) ? col[(size_t)(l0-1) * (2*D_MODEL)] : 0.f;

#pragma unroll
    for (int i = 0; i < 8; i++) {
        float x3 = col[(size_t)(l0+i) * (2*D_MODEL)];
        float s = bias + w0*x0 + w1*x1 + w2*x2 + w3*x3;
        float v = s / (1.f + expf(-s));
        a_h[((size_t)(b * L_SEQ + l0 + i)) * D_MODEL + d] = __float2half_rn(v);
        x0 = x1; x1 = x2; x2 = x3;
    }
}

// ================= chunked scan (delta fp16) =================
__global__ __launch_bounds__(128)
void scan_phase1(const __half* __restrict__ delta_h,
                 const __half* __restrict__ a_h,
                 const float* __restrict__ tall,
                 const float* __restrict__ A_param,
                 float* __restrict__ Pb,
                 float* __restrict__ hendb)
{
    int gid = blockIdx.x * blockDim.x + threadIdx.x;
    int ch = gid & (NCHAN - 1);
    int chunk = gid >> 12;
    int b = ch >> 11;
    int d = ch & (D_MODEL - 1);

    float expA[D_STATE];
#pragma unroll
    for (int s = 0; s < D_STATE; s++) expA[s] = expf(-A_param[(size_t)d * D_STATE + s]);

    float h[D_STATE], P[D_STATE];
#pragma unroll
    for (int s = 0; s < D_STATE; s++) { h[s] = 0.f; P[s] = 1.f; }

    const int l0 = chunk * LCHUNK;
    for (int l = l0; l < l0 + LCHUNK; l++) {
        const size_t row = (size_t)b * L_SEQ + l;
        float dlt = __half2float(delta_h[row * D_MODEL + d]);
        float av  = __half2float(a_h[row * D_MODEL + d]);
        const float4* Bp = (const float4*)(tall + row * N_BCT);
        float4 B0 = Bp[0], B1 = Bp[1], B2 = Bp[2], B3 = Bp[3];
        float Bv[16] = {B0.x,B0.y,B0.z,B0.w, B1.x,B1.y,B1.z,B1.w,
                        B2.x,B2.y,B2.z,B2.w, B3.x,B3.y,B3.z,B3.w};
        float xc = dlt * av;
#pragma unroll
        for (int s = 0; s < D_STATE; s++) {
            float Ab = expA[s] * dlt;
            h[s] = fmaf(Ab, h[s], Bv[s] * xc);
            P[s] *= Ab;
        }
    }
    float4* Pd = (float4*)(Pb    + ((size_t)chunk * NCHAN + ch) * D_STATE);
    float4* Hd = (float4*)(hendb + ((size_t)chunk * NCHAN + ch) * D_STATE);
#pragma unroll
    for (int q = 0; q < 4; q++) {
        Pd[q] = make_float4(P[q*4], P[q*4+1], P[q*4+2], P[q*4+3]);
        Hd[q] = make_float4(h[q*4], h[q*4+1], h[q*4+2], h[q*4+3]);
    }
}

__global__ __launch_bounds__(128)
void scan_phase2(const float* __restrict__ Pb,
                 const float* __restrict__ hendb,
                 float* __restrict__ hstartb)
{
    int ch = blockIdx.x * blockDim.x + threadIdx.x;
    if (ch >= NCHAN) return;
    float hs[D_STATE];
#pragma unroll
    for (int s = 0; s < D_STATE; s++) hs[s] = 0.f;
    for (int c = 0; c < NCHUNK; c++) {
        float4* Hs = (float4*)(hstartb + ((size_t)c * NCHAN + ch) * D_STATE);
#pragma unroll
        for (int q = 0; q < 4; q++)
            Hs[q] = make_float4(hs[q*4], hs[q*4+1], hs[q*4+2], hs[q*4+3]);
        const float4* Pd = (const float4*)(Pb    + ((size_t)c * NCHAN + ch) * D_STATE);
        const float4* He = (const float4*)(hendb + ((size_t)c * NCHAN + ch) * D_STATE);
#pragma unroll
        for (int q = 0; q < 4; q++) {
            float4 p = Pd[q], e = He[q];
            hs[q*4+0] = fmaf(p.x, hs[q*4+0], e.x);
            hs[q*4+1] = fmaf(p.y, hs[q*4+1], e.y);
            hs[q*4+2] = fmaf(p.z, hs[q*4+2], e.z);
            hs[q*4+3] = fmaf(p.w, hs[q*4+3], e.w);
        }
    }
}

__global__ __launch_bounds__(128)
void scan_phase3(const __half* __restrict__ delta_h,
                 const __half* __restrict__ a_h,
                 const float* __restrict__ ab,
                 const float* __restrict__ tall,
                 const float* __restrict__ A_param,
                 const float* __restrict__ D_param,
                 const float* __restrict__ hstartb,
                 __half* __restrict__ y_h)
{
    int gid = blockIdx.x * blockDim.x + threadIdx.x;
    int ch = gid & (NCHAN - 1);
    int chunk = gid >> 12;
    int b = ch >> 11;
    int d = ch & (D_MODEL - 1);

    float expA[D_STATE];
#pragma unroll
    for (int s = 0; s < D_STATE; s++) expA[s] = expf(-A_param[(size_t)d * D_STATE + s]);
    const float Dp = D_param[d];

    float h[D_STATE];
    const float4* Hs = (const float4*)(hstartb + ((size_t)chunk * NCHAN + ch) * D_STATE);
#pragma unroll
    for (int q = 0; q < 4; q++) {
        float4 v = Hs[q];
        h[q*4+0] = v.x; h[q*4+1] = v.y; h[q*4+2] = v.z; h[q*4+3] = v.w;
    }

    const int l0 = chunk * LCHUNK;
    for (int l = l0; l < l0 + LCHUNK; l++) {
        const size_t row = (size_t)b * L_SEQ + l;
        float dlt = __half2float(delta_h[row * D_MODEL + d]);
        float av  = __half2float(a_h[row * D_MODEL + d]);
        float gt  = ab[row * (2*D_MODEL) + D_MODEL + d];
        const float4* Bp = (const float4*)(tall + row * N_BCT);
        const float4* Cp = (const float4*)(tall + row * N_BCT + 16);
        float4 B0 = Bp[0], B1 = Bp[1], B2 = Bp[2], B3 = Bp[3];
        float4 C0 = Cp[0], C1 = Cp[1], C2 = Cp[2], C3 = Cp[3];
        float Bv[16] = {B0.x,B0.y,B0.z,B0.w, B1.x,B1.y,B1.z,B1.w,
                        B2.x,B2.y,B2.z,B2.w, B3.x,B3.y,B3.z,B3.w};
        float Cv[16] = {C0.x,C0.y,C0.z,C0.w, C1.x,C1.y,C1.z,C1.w,
                        C2.x,C2.y,C2.z,C2.w, C3.x,C3.y,C3.z,C3.w};
        float xc = dlt * av;
        float acc0 = 0.f, acc1 = 0.f;
#pragma unroll
        for (int s = 0; s < D_STATE; s += 2) {
            float Ab0 = expA[s]   * dlt;
            float Ab1 = expA[s+1] * dlt;
            h[s]   = fmaf(Ab0, h[s],   Bv[s]   * xc);
            h[s+1] = fmaf(Ab1, h[s+1], Bv[s+1] * xc);
            acc0   = fmaf(h[s],   Cv[s],   acc0);
            acc1   = fmaf(h[s+1], Cv[s+1], acc1);
        }
        float silu_g = gt / (1.f + expf(-gt));
        float yv = (acc0 + acc1 + Dp * av) * silu_g;
        y_h[row * D_MODEL + d] = __float2half_rn(yv);
    }
}

// ---------------- launch ----------------
extern "C" void kernel_launch(void* const* d_in, const int* in_sizes, int n_in,
                              void* d_out, int out_size)
{
    const float* seq     = (const float*)d_in[0];
    const float* w_in    = (const float*)d_in[1];
    const float* w_out   = (const float*)d_in[2];
    const float* w_B     = (const float*)d_in[3];
    const float* w_C     = (const float*)d_in[4];
    const float* w_D1    = (const float*)d_in[5];
    const float* w_D2    = (const float*)d_in[6];
    const float* conv_w  = (const float*)d_in[7];
    const float* conv_b  = (const float*)d_in[8];
    const float* A_param = (const float*)d_in[9];
    const float* D_param = (const float*)d_in[10];
    float* out = (float*)d_out;

    float *ab_p, *tall_p, *P_p, *hend_p, *hstart_p, *outp_p;
    __half *delta_h, *seq_h, *win_h, *a_h, *wbcd_h, *wd2_h, *t_h, *wout_h, *y_h;
    cudaGetSymbolAddress((void**)&ab_p,    g_ab);
    cudaGetSymbolAddress((void**)&tall_p,  g_tall);
    cudaGetSymbolAddress((void**)&P_p,     g_P);
    cudaGetSymbolAddress((void**)&hend_p,  g_hend);
    cudaGetSymbolAddress((void**)&hstart_p,g_hstart);
    cudaGetSymbolAddress((void**)&outp_p,  g_outp);
    cudaGetSymbolAddress((void**)&delta_h, g_delta_h);
    cudaGetSymbolAddress((void**)&seq_h,   g_seq_h);
    cudaGetSymbolAddress((void**)&win_h,   g_win_h);
    cudaGetSymbolAddress((void**)&a_h,     g_a_h);
    cudaGetSymbolAddress((void**)&wbcd_h,  g_wbcd_h);
    cudaGetSymbolAddress((void**)&wd2_h,   g_wd2_h);
    cudaGetSymbolAddress((void**)&t_h,     g_t_h);
    cudaGetSymbolAddress((void**)&wout_h,  g_wout_h);
    cudaGetSymbolAddress((void**)&y_h,     g_y_h);

    cudaFuncSetAttribute(mma_gemm<2>, cudaFuncAttributeMaxDynamicSharedMemorySize, GSMEM);
    cudaFuncSetAttribute(mma_gemm<3>, cudaFuncAttributeMaxDynamicSharedMemorySize, GSMEM);
    cudaFuncSetAttribute(mma_gemm_big, cudaFuncAttributeMaxDynamicSharedMemorySize, GSMEM_BIG);

    static cudaStream_t s2 = nullptr;
    static cudaEvent_t evFork = nullptr, evJoin = nullptr;
    if (s2 == nullptr) {
        cudaStreamCreateWithFlags(&s2, cudaStreamNonBlocking);
        cudaEventCreateWithFlags(&evFork, cudaEventDisableTiming);
        cudaEventCreateWithFlags(&evJoin, cudaEventDisableTiming);
    }

    // fork: side stream converts weights not needed until step 3+
    cudaEventRecord(evFork, 0);
    cudaStreamWaitEvent(s2, evFork, 0);
    convert_fp16_2<<<(((D_MODEL*D_DISCR + D_IN*D_MODEL) >> 3) + 255)/256, 256, 0, s2>>>(
        w_D2, wd2_h, D_MODEL * D_DISCR, w_out, wout_h, D_IN * D_MODEL);
    build_wbcd<<<((N_BCT*D_MODEL >> 3) + 255)/256, 256, 0, s2>>>(w_B, w_C, w_D1, wbcd_h);
    cudaEventRecord(evJoin, s2);

    // main stream: converts needed immediately (fused into one launch)
    convert_fp16_2<<<(((M_ROWS*D_IN + 2*D_MODEL*D_IN) >> 3) + 255)/256, 256>>>(
        seq, seq_h, M_ROWS * D_IN, w_in, win_h, 2*D_MODEL * D_IN);

    // 1) in_proj: ab = seq @ w_in^T   (2048 x 4096, K=1024) — big tile
    {
        dim3 grid(M_ROWS/256, (2*D_MODEL)/128, 1);
        mma_gemm_big<<<grid, 256, GSMEM_BIG>>>(M_ROWS, 2*D_MODEL, D_IN,
                                               seq_h, win_h, ab_p, D_IN);
    }
    // 2) depthwise conv + bias + silu -> a_h fp16 (register-rolling)
    {
        int n = (B_SZ * L_SEQ * D_MODEL) / 8;
        conv_silu_kernel<<<(n + 255)/256, 256>>>(ab_p, conv_w, conv_b, a_h);
    }
    cudaMemsetAsync(tall_p, 0, (size_t)M_ROWS * N_BCT * sizeof(float));

    cudaStreamWaitEvent(0, evJoin, 0);

    // 3) fused BCt: t_all = a @ [w_B|w_C|w_D1|0]^T  (2048 x 256, K=2048), split-K=8
    {
        dim3 grid(M_ROWS/128, N_BCT/128, 8);
        mma_gemm<2><<<grid, 256, GSMEM>>>(M_ROWS, N_BCT, D_MODEL,
                                          a_h, wbcd_h, tall_p, nullptr, D_MODEL/8);
    }
    // 4) t -> fp16
    extract_t<<<((M_ROWS*D_DISCR >> 2) + 255)/256, 256>>>(tall_p, t_h);
    // 5) delta = softplus(D_param + t @ w_D2^T) -> fp16   (2048 x 2048, K=128)
    {
        dim3 grid(M_ROWS/128, D_MODEL/128, 1);
        mma_gemm<3><<<grid, 256, GSMEM>>>(M_ROWS, D_MODEL, D_DISCR,
                                          t_h, wd2_h, (float*)delta_h, D_param, D_DISCR);
    }
    // 6) chunked scan
    scan_phase1<<<(NCHAN*NCHUNK)/128, 128>>>(delta_h, a_h, tall_p, A_param, P_p, hend_p);
    scan_phase2<<<NCHAN/128, 128>>>(P_p, hend_p, hstart_p);
    scan_phase3<<<(NCHAN*NCHUNK)/128, 128>>>(delta_h, a_h, ab_p, tall_p,
                                             A_param, D_param, hstart_p, y_h);
    // 7) out = y @ w_out^T  (2048 x 1024, K=2048) — big tile split-K=2 -> partials
    {
        dim3 grid(M_ROWS/256, D_IN/128, 2);
        mma_gemm_big<<<grid, 256, GSMEM_BIG>>>(M_ROWS, D_IN, D_MODEL,
                                               y_h, wout_h, outp_p, D_MODEL/2);
    }
    // 8) out = p0 + p1
    {
        int n = M_ROWS * D_IN;
        reduce2<<<((n >> 2) + 255)/256, 256>>>(outp_p, out, n);
    }
}

// round 17
// speedup vs baseline: 1.1249x; 1.0531x over previous
#include <cuda_runtime.h>
#include <cuda_fp16.h>
#include <cstdint>
#include <math.h>

// Problem constants
#define B_SZ 2
#define L_SEQ 1024
#define D_IN 1024
#define D_MODEL 2048
#define D_STATE 16
#define D_DISCR 128
#define KER 4
#define M_ROWS (B_SZ * L_SEQ)          // 2048
#define N_BCT 256                      // padded: 16 B + 16 C + 128 D1 + 96 zero
#define NCHUNK 16
#define LCHUNK (L_SEQ / NCHUNK)        // 64
#define NCHAN (B_SZ * D_MODEL)         // 4096

// ---------------- scratch (device globals; no allocation) ----------------
__device__ float g_ab[(size_t)M_ROWS * 2 * D_MODEL];      // in_proj out [2048,4096]
__device__ float g_tall[(size_t)M_ROWS * N_BCT];          // [Bm|Cm|t|pad] fp32
__device__ float g_P[(size_t)NCHUNK * NCHAN * D_STATE];
__device__ float g_hend[(size_t)NCHUNK * NCHAN * D_STATE];
__device__ float g_hstart[(size_t)NCHUNK * NCHAN * D_STATE];
__device__ float g_outp[(size_t)2 * M_ROWS * D_IN];       // out_proj split-K partials
// fp16 operands
__device__ __half g_delta_h[(size_t)M_ROWS * D_MODEL];    // softplus output, fp16
__device__ __half g_seq_h [(size_t)M_ROWS * D_IN];
__device__ __half g_win_h [(size_t)(2*D_MODEL) * D_IN];
__device__ __half g_a_h   [(size_t)M_ROWS * D_MODEL];
__device__ __half g_wbcd_h[(size_t)N_BCT * D_MODEL];
__device__ __half g_wd2_h [(size_t)D_MODEL * D_DISCR];
__device__ __half g_t_h   [(size_t)M_ROWS * D_DISCR];
__device__ __half g_wout_h[(size_t)D_IN * D_MODEL];
__device__ __half g_y_h   [(size_t)M_ROWS * D_MODEL];

// ================= helpers =================
__device__ __forceinline__ uint32_t smem_u32(const void* p) {
    uint32_t a;
    asm("{ .reg .u64 t; cvta.to.shared.u64 t, %1; cvt.u32.u64 %0, t; }" : "=r"(a) : "l"(p));
    return a;
}
__device__ __forceinline__ void ldm4(uint32_t* r, uint32_t addr) {
    asm volatile("ldmatrix.sync.aligned.m8n8.x4.shared.b16 {%0,%1,%2,%3}, [%4];"
                 : "=r"(r[0]), "=r"(r[1]), "=r"(r[2]), "=r"(r[3]) : "r"(addr));
}
__device__ __forceinline__ void mma16816(float* c, const uint32_t* a, const uint32_t* b) {
    asm volatile("mma.sync.aligned.m16n8k16.row.col.f32.f16.f16.f32 "
                 "{%0,%1,%2,%3}, {%4,%5,%6,%7}, {%8,%9}, {%0,%1,%2,%3};"
                 : "+f"(c[0]), "+f"(c[1]), "+f"(c[2]), "+f"(c[3])
                 : "r"(a[0]), "r"(a[1]), "r"(a[2]), "r"(a[3]), "r"(b[0]), "r"(b[1]));
}
__device__ __forceinline__ void cp16(uint32_t dst, const void* src) {
    asm volatile("cp.async.cg.shared.global [%0], [%1], 16;" :: "r"(dst), "l"(src));
}
__device__ __forceinline__ void cp_commit() {
    asm volatile("cp.async.commit_group;" ::: "memory");
}
template<int N>
__device__ __forceinline__ void cp_wait() {
    asm volatile("cp.async.wait_group %0;" :: "n"(N) : "memory");
}
__device__ __forceinline__ uint32_t swz(int r, int byteCol) {
    uint32_t off = (uint32_t)(r * 128 + byteCol);
    return off ^ (((uint32_t)r & 7u) << 4);
}

// ================= pipelined fp16 HMMA NT GEMM (128x128, BK=64) =============
// EPI: 2 atomicAdd (split-K), 3 softplus->fp16 store (C as __half*).
#define STG 32768
#define NSTG 3
#define GSMEM (NSTG * STG)   // 96 KB

template<int EPI>
__global__ __launch_bounds__(256, 2)
void mma_gemm(int M, int N, int K,
              const __half* __restrict__ A,
              const __half* __restrict__ W,
              float* __restrict__ C,
              const float* __restrict__ bias,
              int kPerSplit)
{
    extern __shared__ char smem[];
    const uint32_t sb = smem_u32(smem);
    const int tid = threadIdx.x;
    const int wid = tid >> 5, lane = tid & 31;
    const int wm = wid & 1, wn = wid >> 1;          // 2 x 4 warp grid
    const int row0 = blockIdx.x * 128;
    const int col0 = blockIdx.y * 128;
    const int k0 = blockIdx.z * kPerSplit;
    const int nCh = kPerSplit / 64;

    const char* Ab = (const char*)A;
    const char* Wb = (const char*)W;

    auto issue = [&](int j) {
        const int st = j % NSTG;
        const uint32_t stA = sb + st * STG;
        const uint32_t stB = stA + 16384;
        const int kt = k0 + j * 64;
#pragma unroll
        for (int i = 0; i < 4; i++) {
            int c = i * 256 + tid;
            int r = c >> 3, g = c & 7;
            cp16(stA + swz(r, g * 16),
                 Ab + ((size_t)(row0 + r) * K + kt) * 2 + g * 16);
        }
#pragma unroll
        for (int i = 0; i < 4; i++) {
            int c = i * 256 + tid;
            int r = c >> 3, g = c & 7;
            cp16(stB + swz(r, g * 16),
                 Wb + ((size_t)(col0 + r) * K + kt) * 2 + g * 16);
        }
        cp_commit();
    };

    float acc[4][4][4];
#pragma unroll
    for (int i = 0; i < 4; i++)
#pragma unroll
        for (int j = 0; j < 4; j++)
#pragma unroll
            for (int q = 0; q < 4; q++) acc[i][j][q] = 0.f;

    const int pre = (nCh < NSTG - 1) ? nCh : (NSTG - 1);
    for (int j = 0; j < pre; j++) issue(j);

    const int ra_l = (lane & 15);
    const int ga_l = (lane >> 4) * 16;
    const int rb_l = ((lane >> 4) & 1) * 8 + (lane & 7);
    const int gb_l = ((lane >> 3) & 1) * 16;

    for (int j = 0; j < nCh; j++) {
        int newer = nCh - 1 - j; if (newer > NSTG - 2) newer = NSTG - 2;
        if (newer >= 1) cp_wait<1>(); else cp_wait<0>();
        __syncthreads();

        if (j + NSTG - 1 < nCh) issue(j + NSTG - 1);

        const int st = j % NSTG;
        const uint32_t sA = sb + st * STG;
        const uint32_t sB = sA + 16384;

#pragma unroll
        for (int s = 0; s < 4; s++) {
            uint32_t ah[4][4], bh[2][4];
#pragma unroll
            for (int mi = 0; mi < 4; mi++) {
                int r = wm * 64 + mi * 16 + ra_l;
                ldm4(ah[mi], sA + swz(r, s * 32 + ga_l));
            }
#pragma unroll
            for (int p = 0; p < 2; p++) {
                int r = wn * 32 + p * 16 + rb_l;
                ldm4(bh[p], sB + swz(r, s * 32 + gb_l));
            }
#pragma unroll
            for (int mi = 0; mi < 4; mi++) {
#pragma unroll
                for (int ni = 0; ni < 4; ni++) {
                    mma16816(acc[mi][ni], ah[mi], &bh[ni >> 1][(ni & 1) * 2]);
                }
            }
        }
    }

    const int er = (lane >> 2);
    const int ec = (lane & 3) * 2;
#pragma unroll
    for (int mi = 0; mi < 4; mi++) {
#pragma unroll
        for (int ni = 0; ni < 4; ni++) {
            int r = row0 + wm * 64 + mi * 16 + er;
            int c = col0 + wn * 32 + ni * 8 + ec;
            float v0 = acc[mi][ni][0], v1 = acc[mi][ni][1];
            float v2 = acc[mi][ni][2], v3 = acc[mi][ni][3];
            if (EPI == 3) {
                float b0 = bias[c], b1 = bias[c + 1];
                float x;
                x = b0 + v0; v0 = (x > 20.f) ? x : log1pf(expf(x));
                x = b1 + v1; v1 = (x > 20.f) ? x : log1pf(expf(x));
                x = b0 + v2; v2 = (x > 20.f) ? x : log1pf(expf(x));
                x = b1 + v3; v3 = (x > 20.f) ? x : log1pf(expf(x));
                __half* Ch = (__half*)C;
                *(__half2*)(Ch + (size_t)r * N + c)       = __floats2half2_rn(v0, v1);
                *(__half2*)(Ch + (size_t)(r + 8) * N + c) = __floats2half2_rn(v2, v3);
            } else {
                atomicAdd(C + (size_t)r * N + c,           v0);
                atomicAdd(C + (size_t)r * N + c + 1,       v1);
                atomicAdd(C + (size_t)(r + 8) * N + c,     v2);
                atomicAdd(C + (size_t)(r + 8) * N + c + 1, v3);
            }
        }
    }
}

// ============ big-tile GEMM: 256x128, BK=128, 2 stages; col_base offset =====
// Race-free: prologue fills both stages; wait_group<1> retires group j;
// issue(j+2) only after post-compute barrier. Plain fp32 store;
// gridDim.z>1 writes to per-split partial slice of C.
#define STG_BIG 98304            // 96 KB
#define NSTG_BIG 2
#define GSMEM_BIG (NSTG_BIG * STG_BIG)  // 192 KB

__global__ __launch_bounds__(256, 1)
void mma_gemm_big(int M, int N, int K,
                  const __half* __restrict__ A,
                  const __half* __restrict__ W,
                  float* __restrict__ C,
                  int kPerSplit, int col_base)
{
    extern __shared__ char smem[];
    const uint32_t sb = smem_u32(smem);
    const int tid = threadIdx.x;
    const int wid = tid >> 5, lane = tid & 31;
    const int wm = wid & 3, wn = wid >> 2;          // 4 x 2 warp grid
    const int row0 = blockIdx.x * 256;
    const int col0 = col_base + blockIdx.y * 128;
    const int k0 = blockIdx.z * kPerSplit;
    const int nCh = kPerSplit / 128;

    float* Cz = C + (size_t)blockIdx.z * M * N;

    const char* Ab = (const char*)A;
    const char* Wb = (const char*)W;

    auto issue = [&](int j) {
        const int st = j & (NSTG_BIG - 1);
        const uint32_t stA = sb + st * STG_BIG;
        const uint32_t stB = stA + 65536;
        const int kt = k0 + j * 128;
#pragma unroll
        for (int i = 0; i < 16; i++) {
            int c = i * 256 + tid;
            int r = c >> 4, g = c & 15;
            int half = g >> 3, gg = g & 7;
            cp16(stA + half * 32768 + swz(r, gg * 16),
                 Ab + ((size_t)(row0 + r) * K + kt + g * 8) * 2);
        }
#pragma unroll
        for (int i = 0; i < 8; i++) {
            int c = i * 256 + tid;
            int r = c >> 4, g = c & 15;
            int half = g >> 3, gg = g & 7;
            cp16(stB + half * 16384 + swz(r, gg * 16),
                 Wb + ((size_t)(col0 + r) * K + kt + g * 8) * 2);
        }
        cp_commit();
    };

    float acc[4][8][4];
#pragma unroll
    for (int i = 0; i < 4; i++)
#pragma unroll
        for (int j = 0; j < 8; j++)
#pragma unroll
            for (int q = 0; q < 4; q++) acc[i][j][q] = 0.f;

    issue(0);
    if (nCh > 1) issue(1);

    const int ra_l = (lane & 15);
    const int ga_l = (lane >> 4) * 16;
    const int rb_l = ((lane >> 4) & 1) * 8 + (lane & 7);
    const int gb_l = ((lane >> 3) & 1) * 16;

    for (int j = 0; j < nCh; j++) {
        if (j + 1 < nCh) cp_wait<1>(); else cp_wait<0>();
        __syncthreads();

        const int st = j & (NSTG_BIG - 1);
        const uint32_t sA = sb + st * STG_BIG;
        const uint32_t sB = sA + 65536;

#pragma unroll
        for (int s = 0; s < 8; s++) {
            const uint32_t hA = sA + (s >> 2) * 32768;
            const uint32_t hB = sB + (s >> 2) * 16384;
            const int so = (s & 3) * 32;
            uint32_t ah[4][4], bh[4][4];
#pragma unroll
            for (int mi = 0; mi < 4; mi++) {
                int r = wm * 64 + mi * 16 + ra_l;
                ldm4(ah[mi], hA + swz(r, so + ga_l));
            }
#pragma unroll
            for (int p = 0; p < 4; p++) {
                int r = wn * 64 + p * 16 + rb_l;
                ldm4(bh[p], hB + swz(r, so + gb_l));
            }
#pragma unroll
            for (int mi = 0; mi < 4; mi++) {
#pragma unroll
                for (int ni = 0; ni < 8; ni++) {
                    mma16816(acc[mi][ni], ah[mi], &bh[ni >> 1][(ni & 1) * 2]);
                }
            }
        }

        if (j + 2 < nCh) {
            __syncthreads();
            issue(j + 2);
        }
    }

    const int er = (lane >> 2);
    const int ec = (lane & 3) * 2;
#pragma unroll
    for (int mi = 0; mi < 4; mi++) {
#pragma unroll
        for (int ni = 0; ni < 8; ni++) {
            int r = row0 + wm * 64 + mi * 16 + er;
            int c = col0 + wn * 64 + ni * 8 + ec;
            float2 p0 = {acc[mi][ni][0], acc[mi][ni][1]};
            float2 p1 = {acc[mi][ni][2], acc[mi][ni][3]};
            *(float2*)(Cz + (size_t)r * N + c)       = p0;
            *(float2*)(Cz + (size_t)(r + 8) * N + c) = p1;
        }
    }
}

// ================= reduce two split-K partials -> output =================
__global__ void reduce2(const float* __restrict__ p, float* __restrict__ out, int n)
{
    int idx = blockIdx.x * blockDim.x + threadIdx.x;
    if (idx >= (n >> 2)) return;
    float4 a = *(const float4*)(p + (size_t)idx * 4);
    float4 b = *(const float4*)(p + (size_t)n + (size_t)idx * 4);
    float4 r = {a.x + b.x, a.y + b.y, a.z + b.z, a.w + b.w};
    *(float4*)(out + (size_t)idx * 4) = r;
}

// ================= converts =================
__global__ void convert_fp16_2(const float* __restrict__ X1, __half* __restrict__ Y1, int n1,
                               const float* __restrict__ X2, __half* __restrict__ Y2, int n2)
{
    int idx = blockIdx.x * blockDim.x + threadIdx.x;
    int tot = (n1 + n2) >> 3;
    if (idx >= tot) return;
    const float* X; __half* Y; size_t off;
    if (idx < (n1 >> 3)) { X = X1; Y = Y1; off = (size_t)idx * 8; }
    else { X = X2; Y = Y2; off = (size_t)(idx - (n1 >> 3)) * 8; }
    float4 v0 = *(const float4*)(X + off);
    float4 v1 = *(const float4*)(X + off + 4);
    union { uint4 u; __half h[8]; } o;
    o.h[0] = __float2half_rn(v0.x); o.h[1] = __float2half_rn(v0.y);
    o.h[2] = __float2half_rn(v0.z); o.h[3] = __float2half_rn(v0.w);
    o.h[4] = __float2half_rn(v1.x); o.h[5] = __float2half_rn(v1.y);
    o.h[6] = __float2half_rn(v1.z); o.h[7] = __float2half_rn(v1.w);
    *(uint4*)(Y + off) = o.u;
}

__global__ void build_wbcd(const float* __restrict__ wB, const float* __restrict__ wC,
                           const float* __restrict__ wD1, __half* __restrict__ Y)
{
    int idx = blockIdx.x * blockDim.x + threadIdx.x;
    if (idx >= (N_BCT * D_MODEL) >> 3) return;
    int r = idx / (D_MODEL >> 3);
    int k = (idx % (D_MODEL >> 3)) << 3;
    const float* src = nullptr;
    if (r < 16)       src = wB  + (size_t)r * D_MODEL + k;
    else if (r < 32)  src = wC  + (size_t)(r - 16) * D_MODEL + k;
    else if (r < 160) src = wD1 + (size_t)(r - 32) * D_MODEL + k;
    union { uint4 u; __half h[8]; } o;
    if (src) {
        float4 v0 = *(const float4*)src;
        float4 v1 = *(const float4*)(src + 4);
        o.h[0]=__float2half_rn(v0.x); o.h[1]=__float2half_rn(v0.y);
        o.h[2]=__float2half_rn(v0.z); o.h[3]=__float2half_rn(v0.w);
        o.h[4]=__float2half_rn(v1.x); o.h[5]=__float2half_rn(v1.y);
        o.h[6]=__float2half_rn(v1.z); o.h[7]=__float2half_rn(v1.w);
    } else {
        o.u = make_uint4(0,0,0,0);
    }
    *(uint4*)(Y + (size_t)r * D_MODEL + k) = o.u;
}

__global__ void extract_t(const float* __restrict__ tall, __half* __restrict__ Y)
{
    int idx = blockIdx.x * blockDim.x + threadIdx.x;
    if (idx >= (M_ROWS * D_DISCR) >> 2) return;
    int r = idx / (D_DISCR >> 2);
    int c = (idx % (D_DISCR >> 2)) << 2;
    float4 v = *(const float4*)(tall + (size_t)r * N_BCT + 32 + c);
    union { uint2 u; __half h[4]; } o;
    o.h[0]=__float2half_rn(v.x); o.h[1]=__float2half_rn(v.y);
    o.h[2]=__float2half_rn(v.z); o.h[3]=__float2half_rn(v.w);
    *(uint2*)(Y + (size_t)r * D_DISCR + c) = o.u;
}

// ------ depthwise causal conv: register-rolling window, 8 l per thread ------
__global__ void conv_silu_kernel(const float* __restrict__ ab,
                                 const float* __restrict__ cw,
                                 const float* __restrict__ cb,
                                 __half* __restrict__ a_h)
{
    int idx = blockIdx.x * blockDim.x + threadIdx.x;   // over NCHAN * L/8
    if (idx >= (B_SZ * L_SEQ * D_MODEL) / 8) return;
    int d   = idx & (D_MODEL - 1);
    int blk = idx >> 11;                // b * (L/8) + lblk
    int lblk = blk & (L_SEQ / 8 - 1);
    int b    = blk >> 7;                // L/8 = 128
    int l0   = lblk * 8;

    float w0 = cw[d*4+0], w1 = cw[d*4+1], w2 = cw[d*4+2], w3 = cw[d*4+3];
    float bias = cb[d];
    const float* col = ab + ((size_t)b * L_SEQ) * (2*D_MODEL) + d;

    float x0 = (l0 >= 3) ? col[(size_t)(l0-3) * (2*D_MODEL)] : 0.f;
    float x1 = (l0 >= 2) ? col[(size_t)(l0-2) * (2*D_MODEL)] : 0.f;
    float x2 = (l0 >= 1) ? col[(size_t)(l0-1) * (2*D_MODEL)] : 0.f;

#pragma unroll
    for (int i = 0; i < 8; i++) {
        float x3 = col[(size_t)(l0+i) * (2*D_MODEL)];
        float s = bias + w0*x0 + w1*x1 + w2*x2 + w3*x3;
        float v = s / (1.f + expf(-s));
        a_h[((size_t)(b * L_SEQ + l0 + i)) * D_MODEL + d] = __float2half_rn(v);
        x0 = x1; x1 = x2; x2 = x3;
    }
}

// ================= chunked scan (delta fp16) =================
__global__ __launch_bounds__(128)
void scan_phase1(const __half* __restrict__ delta_h,
                 const __half* __restrict__ a_h,
                 const float* __restrict__ tall,
                 const float* __restrict__ A_param,
                 float* __restrict__ Pb,
                 float* __restrict__ hendb)
{
    int gid = blockIdx.x * blockDim.x + threadIdx.x;
    int ch = gid & (NCHAN - 1);
    int chunk = gid >> 12;
    int b = ch >> 11;
    int d = ch & (D_MODEL - 1);

    float expA[D_STATE];
#pragma unroll
    for (int s = 0; s < D_STATE; s++) expA[s] = expf(-A_param[(size_t)d * D_STATE + s]);

    float h[D_STATE], P[D_STATE];
#pragma unroll
    for (int s = 0; s < D_STATE; s++) { h[s] = 0.f; P[s] = 1.f; }

    const int l0 = chunk * LCHUNK;
    for (int l = l0; l < l0 + LCHUNK; l++) {
        const size_t row = (size_t)b * L_SEQ + l;
        float dlt = __half2float(delta_h[row * D_MODEL + d]);
        float av  = __half2float(a_h[row * D_MODEL + d]);
        const float4* Bp = (const float4*)(tall + row * N_BCT);
        float4 B0 = Bp[0], B1 = Bp[1], B2 = Bp[2], B3 = Bp[3];
        float Bv[16] = {B0.x,B0.y,B0.z,B0.w, B1.x,B1.y,B1.z,B1.w,
                        B2.x,B2.y,B2.z,B2.w, B3.x,B3.y,B3.z,B3.w};
        float xc = dlt * av;
#pragma unroll
        for (int s = 0; s < D_STATE; s++) {
            float Ab = expA[s] * dlt;
            h[s] = fmaf(Ab, h[s], Bv[s] * xc);
            P[s] *= Ab;
        }
    }
    float4* Pd = (float4*)(Pb    + ((size_t)chunk * NCHAN + ch) * D_STATE);
    float4* Hd = (float4*)(hendb + ((size_t)chunk * NCHAN + ch) * D_STATE);
#pragma unroll
    for (int q = 0; q < 4; q++) {
        Pd[q] = make_float4(P[q*4], P[q*4+1], P[q*4+2], P[q*4+3]);
        Hd[q] = make_float4(h[q*4], h[q*4+1], h[q*4+2], h[q*4+3]);
    }
}

__global__ __launch_bounds__(128)
void scan_phase2(const float* __restrict__ Pb,
                 const float* __restrict__ hendb,
                 float* __restrict__ hstartb)
{
    int ch = blockIdx.x * blockDim.x + threadIdx.x;
    if (ch >= NCHAN) return;
    float hs[D_STATE];
#pragma unroll
    for (int s = 0; s < D_STATE; s++) hs[s] = 0.f;
    for (int c = 0; c < NCHUNK; c++) {
        float4* Hs = (float4*)(hstartb + ((size_t)c * NCHAN + ch) * D_STATE);
#pragma unroll
        for (int q = 0; q < 4; q++)
            Hs[q] = make_float4(hs[q*4], hs[q*4+1], hs[q*4+2], hs[q*4+3]);
        const float4* Pd = (const float4*)(Pb    + ((size_t)c * NCHAN + ch) * D_STATE);
        const float4* He = (const float4*)(hendb + ((size_t)c * NCHAN + ch) * D_STATE);
#pragma unroll
        for (int q = 0; q < 4; q++) {
            float4 p = Pd[q], e = He[q];
            hs[q*4+0] = fmaf(p.x, hs[q*4+0], e.x);
            hs[q*4+1] = fmaf(p.y, hs[q*4+1], e.y);
            hs[q*4+2] = fmaf(p.z, hs[q*4+2], e.z);
            hs[q*4+3] = fmaf(p.w, hs[q*4+3], e.w);
        }
    }
}

__global__ __launch_bounds__(128)
void scan_phase3(const __half* __restrict__ delta_h,
                 const __half* __restrict__ a_h,
                 const float* __restrict__ ab,
                 const float* __restrict__ tall,
                 const float* __restrict__ A_param,
                 const float* __restrict__ D_param,
                 const float* __restrict__ hstartb,
                 __half* __restrict__ y_h)
{
    int gid = blockIdx.x * blockDim.x + threadIdx.x;
    int ch = gid & (NCHAN - 1);
    int chunk = gid >> 12;
    int b = ch >> 11;
    int d = ch & (D_MODEL - 1);

    float expA[D_STATE];
#pragma unroll
    for (int s = 0; s < D_STATE; s++) expA[s] = expf(-A_param[(size_t)d * D_STATE + s]);
    const float Dp = D_param[d];

    float h[D_STATE];
    const float4* Hs = (const float4*)(hstartb + ((size_t)chunk * NCHAN + ch) * D_STATE);
#pragma unroll
    for (int q = 0; q < 4; q++) {
        float4 v = Hs[q];
        h[q*4+0] = v.x; h[q*4+1] = v.y; h[q*4+2] = v.z; h[q*4+3] = v.w;
    }

    const int l0 = chunk * LCHUNK;
    for (int l = l0; l < l0 + LCHUNK; l++) {
        const size_t row = (size_t)b * L_SEQ + l;
        float dlt = __half2float(delta_h[row * D_MODEL + d]);
        float av  = __half2float(a_h[row * D_MODEL + d]);
        float gt  = ab[row * (2*D_MODEL) + D_MODEL + d];
        const float4* Bp = (const float4*)(tall + row * N_BCT);
        const float4* Cp = (const float4*)(tall + row * N_BCT + 16);
        float4 B0 = Bp[0], B1 = Bp[1], B2 = Bp[2], B3 = Bp[3];
        float4 C0 = Cp[0], C1 = Cp[1], C2 = Cp[2], C3 = Cp[3];
        float Bv[16] = {B0.x,B0.y,B0.z,B0.w, B1.x,B1.y,B1.z,B1.w,
                        B2.x,B2.y,B2.z,B2.w, B3.x,B3.y,B3.z,B3.w};
        float Cv[16] = {C0.x,C0.y,C0.z,C0.w, C1.x,C1.y,C1.z,C1.w,
                        C2.x,C2.y,C2.z,C2.w, C3.x,C3.y,C3.z,C3.w};
        float xc = dlt * av;
        float acc0 = 0.f, acc1 = 0.f;
#pragma unroll
        for (int s = 0; s < D_STATE; s += 2) {
            float Ab0 = expA[s]   * dlt;
            float Ab1 = expA[s+1] * dlt;
            h[s]   = fmaf(Ab0, h[s],   Bv[s]   * xc);
            h[s+1] = fmaf(Ab1, h[s+1], Bv[s+1] * xc);
            acc0   = fmaf(h[s],   Cv[s],   acc0);
            acc1   = fmaf(h[s+1], Cv[s+1], acc1);
        }
        float silu_g = gt / (1.f + expf(-gt));
        float yv = (acc0 + acc1 + Dp * av) * silu_g;
        y_h[row * D_MODEL + d] = __float2half_rn(yv);
    }
}

// ---------------- launch ----------------
extern "C" void kernel_launch(void* const* d_in, const int* in_sizes, int n_in,
                              void* d_out, int out_size)
{
    const float* seq     = (const float*)d_in[0];
    const float* w_in    = (const float*)d_in[1];
    const float* w_out   = (const float*)d_in[2];
    const float* w_B     = (const float*)d_in[3];
    const float* w_C     = (const float*)d_in[4];
    const float* w_D1    = (const float*)d_in[5];
    const float* w_D2    = (const float*)d_in[6];
    const float* conv_w  = (const float*)d_in[7];
    const float* conv_b  = (const float*)d_in[8];
    const float* A_param = (const float*)d_in[9];
    const float* D_param = (const float*)d_in[10];
    float* out = (float*)d_out;

    float *ab_p, *tall_p, *P_p, *hend_p, *hstart_p, *outp_p;
    __half *delta_h, *seq_h, *win_h, *a_h, *wbcd_h, *wd2_h, *t_h, *wout_h, *y_h;
    cudaGetSymbolAddress((void**)&ab_p,    g_ab);
    cudaGetSymbolAddress((void**)&tall_p,  g_tall);
    cudaGetSymbolAddress((void**)&P_p,     g_P);
    cudaGetSymbolAddress((void**)&hend_p,  g_hend);
    cudaGetSymbolAddress((void**)&hstart_p,g_hstart);
    cudaGetSymbolAddress((void**)&outp_p,  g_outp);
    cudaGetSymbolAddress((void**)&delta_h, g_delta_h);
    cudaGetSymbolAddress((void**)&seq_h,   g_seq_h);
    cudaGetSymbolAddress((void**)&win_h,   g_win_h);
    cudaGetSymbolAddress((void**)&a_h,     g_a_h);
    cudaGetSymbolAddress((void**)&wbcd_h,  g_wbcd_h);
    cudaGetSymbolAddress((void**)&wd2_h,   g_wd2_h);
    cudaGetSymbolAddress((void**)&t_h,     g_t_h);
    cudaGetSymbolAddress((void**)&wout_h,  g_wout_h);
    cudaGetSymbolAddress((void**)&y_h,     g_y_h);

    cudaFuncSetAttribute(mma_gemm<2>, cudaFuncAttributeMaxDynamicSharedMemorySize, GSMEM);
    cudaFuncSetAttribute(mma_gemm<3>, cudaFuncAttributeMaxDynamicSharedMemorySize, GSMEM);
    cudaFuncSetAttribute(mma_gemm_big, cudaFuncAttributeMaxDynamicSharedMemorySize, GSMEM_BIG);

    static cudaStream_t s2 = nullptr;
    static cudaEvent_t evFork = nullptr, evCvt = nullptr, evW = nullptr, evGate = nullptr;
    if (s2 == nullptr) {
        cudaStreamCreateWithFlags(&s2, cudaStreamNonBlocking);
        cudaEventCreateWithFlags(&evFork, cudaEventDisableTiming);
        cudaEventCreateWithFlags(&evCvt,  cudaEventDisableTiming);
        cudaEventCreateWithFlags(&evW,    cudaEventDisableTiming);
        cudaEventCreateWithFlags(&evGate, cudaEventDisableTiming);
    }

    // fork: side stream prepares weights + tall memset
    cudaEventRecord(evFork, 0);
    cudaStreamWaitEvent(s2, evFork, 0);
    convert_fp16_2<<<(((D_MODEL*D_DISCR + D_IN*D_MODEL) >> 3) + 255)/256, 256, 0, s2>>>(
        w_D2, wd2_h, D_MODEL * D_DISCR, w_out, wout_h, D_IN * D_MODEL);
    build_wbcd<<<((N_BCT*D_MODEL >> 3) + 255)/256, 256, 0, s2>>>(w_B, w_C, w_D1, wbcd_h);
    cudaMemsetAsync(tall_p, 0, (size_t)M_ROWS * N_BCT * sizeof(float), s2);
    cudaEventRecord(evW, s2);

    // main stream: seq + w_in converts (needed by both in_proj halves)
    convert_fp16_2<<<(((M_ROWS*D_IN + 2*D_MODEL*D_IN) >> 3) + 255)/256, 256>>>(
        seq, seq_h, M_ROWS * D_IN, w_in, win_h, 2*D_MODEL * D_IN);
    cudaEventRecord(evCvt, 0);

    // side stream: gate-half in_proj (cols 2048..4095), overlaps midsection
    cudaStreamWaitEvent(s2, evCvt, 0);
    {
        dim3 grid(M_ROWS/256, D_MODEL/128, 1);   // 8 x 16 = 128 CTAs
        mma_gemm_big<<<grid, 256, GSMEM_BIG, s2>>>(M_ROWS, 2*D_MODEL, D_IN,
                                                   seq_h, win_h, ab_p, D_IN, D_MODEL);
    }
    cudaEventRecord(evGate, s2);

    // main: a-half in_proj (cols 0..2047), single wave
    {
        dim3 grid(M_ROWS/256, D_MODEL/128, 1);   // 128 CTAs
        mma_gemm_big<<<grid, 256, GSMEM_BIG>>>(M_ROWS, 2*D_MODEL, D_IN,
                                               seq_h, win_h, ab_p, D_IN, 0);
    }
    // 2) depthwise conv + bias + silu -> a_h fp16 (register-rolling)
    {
        int n = (B_SZ * L_SEQ * D_MODEL) / 8;
        conv_silu_kernel<<<(n + 255)/256, 256>>>(ab_p, conv_w, conv_b, a_h);
    }
    cudaStreamWaitEvent(0, evW, 0);

    // 3) fused BCt: t_all = a @ [w_B|w_C|w_D1|0]^T  (2048 x 256, K=2048), split-K=8
    {
        dim3 grid(M_ROWS/128, N_BCT/128, 8);
        mma_gemm<2><<<grid, 256, GSMEM>>>(M_ROWS, N_BCT, D_MODEL,
                                          a_h, wbcd_h, tall_p, nullptr, D_MODEL/8);
    }
    // 4) t -> fp16
    extract_t<<<((M_ROWS*D_DISCR >> 2) + 255)/256, 256>>>(tall_p, t_h);
    // 5) delta = softplus(D_param + t @ w_D2^T) -> fp16   (2048 x 2048, K=128)
    {
        dim3 grid(M_ROWS/128, D_MODEL/128, 1);
        mma_gemm<3><<<grid, 256, GSMEM>>>(M_ROWS, D_MODEL, D_DISCR,
                                          t_h, wd2_h, (float*)delta_h, D_param, D_DISCR);
    }
    // 6) chunked scan (phase3 needs gate -> join side stream)
    scan_phase1<<<(NCHAN*NCHUNK)/128, 128>>>(delta_h, a_h, tall_p, A_param, P_p, hend_p);
    scan_phase2<<<NCHAN/128, 128>>>(P_p, hend_p, hstart_p);
    cudaStreamWaitEvent(0, evGate, 0);
    scan_phase3<<<(NCHAN*NCHUNK)/128, 128>>>(delta_h, a_h, ab_p, tall_p,
                                             A_param, D_param, hstart_p, y_h);
    // 7) out = y @ w_out^T  (2048 x 1024, K=2048) — big tile split-K=2 -> partials
    {
        dim3 grid(M_ROWS/256, D_IN/128, 2);
        mma_gemm_big<<<grid, 256, GSMEM_BIG>>>(M_ROWS, D_IN, D_MODEL,
                                               y_h, wout_h, outp_p, D_MODEL/2, 0);
    }
    // 8) out = p0 + p1
    {
        int n = M_ROWS * D_IN;
        reduce2<<<((n >> 2) + 255)/256, 256>>>(outp_p, out, n);
    }
}